// round 9
// baseline (speedup 1.0000x reference)
#include <cuda_runtime.h>

#define NMAX 50000
#define EMAXE 400000
#define ETOTMAX (EMAXE + NMAX)
#define NEG_INF __int_as_float(0xff800000)

// Scratch (static device globals — allocation-free)
__device__ float g_A[NMAX * 256];       // feature buffer
__device__ float g_B[NMAX * 256];       // transformed features h = A @ W
__device__ float g_ssrc[NMAX * 4];      // per-node src attention logits [N,H]
__device__ float g_sdst[NMAX * 4];      // per-node dst attention logits [N,H]
__device__ int   g_csr_src[ETOTMAX];    // CSR: src ids grouped by dst
__device__ int   g_rowptr[NMAX + 1];    // CSR row pointers
__device__ int   g_wptr[NMAX];          // counts / write cursors (0 at start of every run)
__device__ int   g_blksum[260];         // scan partials

__device__ __forceinline__ unsigned f2tf32(float f) {
    unsigned u;
    asm("cvt.rna.tf32.f32 %0, %1;" : "=r"(u) : "f"(f));
    return u;
}

__device__ __forceinline__ float pick4(float4 v, int i) {
    float ab = (i & 1) ? v.y : v.x;
    float cd = (i & 1) ? v.w : v.z;
    return (i & 2) ? cd : ab;
}

// ============================ CSR construction ============================
__global__ void csr_count(const int* __restrict__ ei, int E) {
    int e = blockIdx.x * blockDim.x + threadIdx.x;
    if (e < E) atomicAdd(&g_wptr[ei[E + e]], 1);
}

// per-block sums of (count + 1)  [+1 = self-loop], warp-reduce based
__global__ void scan_part(int n) {
    __shared__ int ws[8];
    int i = blockIdx.x * 256 + threadIdx.x;
    int lane = threadIdx.x & 31, warp = threadIdx.x >> 5;
    int v = (i < n) ? g_wptr[i] + 1 : 0;
#pragma unroll
    for (int o = 16; o; o >>= 1) v += __shfl_xor_sync(0xFFFFFFFFu, v, o);
    if (!lane) ws[warp] = v;
    __syncthreads();
    if (threadIdx.x < 8) {
        int t = ws[threadIdx.x];
#pragma unroll
        for (int o = 4; o; o >>= 1) t += __shfl_xor_sync(0xFFu, t, o, 8);
        if (!threadIdx.x) g_blksum[blockIdx.x] = t;
    }
}

// single-warp exclusive scan over <=256 block sums
__global__ void scan_top(int nb) {
    int lane = threadIdx.x;
    int carry = 0;
    for (int base = 0; base < nb; base += 32) {
        int idx = base + lane;
        int v = (idx < nb) ? g_blksum[idx] : 0;
        int orig = v;
#pragma unroll
        for (int o = 1; o < 32; o <<= 1) {
            int t = __shfl_up_sync(0xFFFFFFFFu, v, o);
            if (lane >= o) v += t;
        }
        if (idx < nb) g_blksum[idx] = carry + v - orig;  // exclusive
        carry += __shfl_sync(0xFFFFFFFFu, v, 31);
    }
}

// per-block scan of (count+1) + global offset; warp-shuffle based (2 barriers)
__global__ void scan_fin(int n) {
    __shared__ int wsum[8];
    int tid = threadIdx.x, i = blockIdx.x * 256 + tid;
    int lane = tid & 31, warp = tid >> 5;
    int v = (i < n) ? g_wptr[i] + 1 : 0;
    int x = v;
#pragma unroll
    for (int o = 1; o < 32; o <<= 1) {
        int t = __shfl_up_sync(0xFFFFFFFFu, x, o);
        if (lane >= o) x += t;
    }
    if (lane == 31) wsum[warp] = x;
    __syncthreads();
    if (warp == 0 && lane < 8) {
        int s = wsum[lane];
#pragma unroll
        for (int o = 1; o < 8; o <<= 1) {
            int t = __shfl_up_sync(0xFFu, s, o, 8);
            if (lane >= o) s += t;
        }
        wsum[lane] = s;  // inclusive warp sums
    }
    __syncthreads();
    int woff = warp ? wsum[warp - 1] : 0;
    int incl = x + woff;
    int off = g_blksum[blockIdx.x];
    if (i < n) { g_rowptr[i] = off + incl - v; g_wptr[i] = 0; }
    if (i == n - 1) g_rowptr[n] = off + incl;
}

__global__ void csr_fill(const int* __restrict__ ei, int E, int Etot) {
    int e = blockIdx.x * blockDim.x + threadIdx.x;
    if (e >= Etot) return;
    int s, d;
    if (e < E) { s = ei[e]; d = ei[E + e]; } else { s = d = e - E; }
    int pos = atomicAdd(&g_wptr[d], 1);
    g_csr_src[g_rowptr[d] + pos] = s;
}

// ============== layer 1 GEMM + fused attention logits ==============
__global__ void gemm_l1_attn(const float* __restrict__ x, const float* __restrict__ W,
                             const float* __restrict__ asrc, const float* __restrict__ adst,
                             float* __restrict__ out, int n) {
    __shared__ float xs[3];
    __shared__ float r1[8], r2[8];
    int node = blockIdx.x;
    if (node >= n) return;
    int tid = threadIdx.x;
    if (tid < 3) xs[tid] = x[node * 3 + tid];
    if (tid == 32) g_wptr[node] = 0;  // cursor reset for next replay
    __syncthreads();
    float acc = xs[0] * W[tid] + xs[1] * W[256 + tid] + xs[2] * W[512 + tid];
    out[(size_t)node * 256 + tid] = acc;
    float p1 = acc * asrc[tid];
    float p2 = acc * adst[tid];
#pragma unroll
    for (int o = 16; o; o >>= 1) {
        p1 += __shfl_xor_sync(0xFFFFFFFFu, p1, o);
        p2 += __shfl_xor_sync(0xFFFFFFFFu, p2, o);
    }
    int warp = tid >> 5, lane = tid & 31;
    if (!lane) { r1[warp] = p1; r2[warp] = p2; }
    __syncthreads();
    if (tid < 4) {
        g_ssrc[node * 4 + tid] = r1[tid * 2] + r1[tid * 2 + 1];
        g_sdst[node * 4 + tid] = r2[tid * 2] + r2[tid * 2 + 1];
    }
}

// =====================================================================
// tf32 tensor-core GEMM, double-buffered smem, fused attn-logit epilogue
// =====================================================================
#define APAD 20
#define BPAD 136

__global__ __launch_bounds__(256) void mma_gemm(
    const float* __restrict__ A, const float* __restrict__ Bw,
    float* __restrict__ C, int M, int N, int K,
    const float* __restrict__ asrc, const float* __restrict__ adst,
    int C_head, int H) {
    __shared__ float As[2][128 * APAD];
    __shared__ float Bs[2][16 * BPAD];

    int tid = threadIdx.x;
    int warp = tid >> 5, lane = tid & 31;
    int gid = lane >> 2, tig = lane & 3;
    int wm = warp & 3, wn = warp >> 2;
    int bm = blockIdx.x * 128, bn = blockIdx.y * 128;

    int am0 = (tid * 2) >> 2, ak0 = ((tid * 2) & 3) * 4;
    int am1 = (tid * 2 + 1) >> 2, ak1 = ((tid * 2 + 1) & 3) * 4;
    int bk0 = (tid * 2) >> 5, bc0 = ((tid * 2) & 31) * 4;
    int bk1 = (tid * 2 + 1) >> 5, bc1 = ((tid * 2 + 1) & 31) * 4;

    float acc[2][8][4];
#pragma unroll
    for (int i = 0; i < 2; i++)
#pragma unroll
        for (int j = 0; j < 8; j++)
#pragma unroll
            for (int r = 0; r < 4; r++) acc[i][j][r] = 0.f;

    float4 ra0, ra1, rb0, rb1;
    {
        ra0 = make_float4(0.f, 0.f, 0.f, 0.f);
        ra1 = ra0; rb0 = ra0; rb1 = ra0;
        if (bm + am0 < M) ra0 = *(const float4*)&A[(size_t)(bm + am0) * K + ak0];
        if (bm + am1 < M) ra1 = *(const float4*)&A[(size_t)(bm + am1) * K + ak1];
        if (bn + bc0 < N) rb0 = *(const float4*)&Bw[(size_t)bk0 * N + bn + bc0];
        if (bn + bc1 < N) rb1 = *(const float4*)&Bw[(size_t)bk1 * N + bn + bc1];
    }
    {
        float* p = &As[0][am0 * APAD + ak0];
        p[0] = __uint_as_float(f2tf32(ra0.x)); p[1] = __uint_as_float(f2tf32(ra0.y));
        p[2] = __uint_as_float(f2tf32(ra0.z)); p[3] = __uint_as_float(f2tf32(ra0.w));
        p = &As[0][am1 * APAD + ak1];
        p[0] = __uint_as_float(f2tf32(ra1.x)); p[1] = __uint_as_float(f2tf32(ra1.y));
        p[2] = __uint_as_float(f2tf32(ra1.z)); p[3] = __uint_as_float(f2tf32(ra1.w));
        p = &Bs[0][bk0 * BPAD + bc0];
        p[0] = __uint_as_float(f2tf32(rb0.x)); p[1] = __uint_as_float(f2tf32(rb0.y));
        p[2] = __uint_as_float(f2tf32(rb0.z)); p[3] = __uint_as_float(f2tf32(rb0.w));
        p = &Bs[0][bk1 * BPAD + bc1];
        p[0] = __uint_as_float(f2tf32(rb1.x)); p[1] = __uint_as_float(f2tf32(rb1.y));
        p[2] = __uint_as_float(f2tf32(rb1.z)); p[3] = __uint_as_float(f2tf32(rb1.w));
    }
    __syncthreads();

    int cur = 0;
    for (int k0 = 0; k0 < K; k0 += 16) {
        bool has_next = (k0 + 16) < K;
        if (has_next) {
            int kn = k0 + 16;
            ra0 = make_float4(0.f, 0.f, 0.f, 0.f);
            ra1 = ra0; rb0 = ra0; rb1 = ra0;
            if (bm + am0 < M) ra0 = *(const float4*)&A[(size_t)(bm + am0) * K + kn + ak0];
            if (bm + am1 < M) ra1 = *(const float4*)&A[(size_t)(bm + am1) * K + kn + ak1];
            if (bn + bc0 < N) rb0 = *(const float4*)&Bw[(size_t)(kn + bk0) * N + bn + bc0];
            if (bn + bc1 < N) rb1 = *(const float4*)&Bw[(size_t)(kn + bk1) * N + bn + bc1];
        }
#pragma unroll
        for (int kk = 0; kk < 16; kk += 8) {
            unsigned af[2][4], bf[8][2];
#pragma unroll
            for (int mt = 0; mt < 2; mt++) {
                int row = wm * 32 + mt * 16 + gid;
                af[mt][0] = __float_as_uint(As[cur][row * APAD + kk + tig]);
                af[mt][1] = __float_as_uint(As[cur][(row + 8) * APAD + kk + tig]);
                af[mt][2] = __float_as_uint(As[cur][row * APAD + kk + tig + 4]);
                af[mt][3] = __float_as_uint(As[cur][(row + 8) * APAD + kk + tig + 4]);
            }
#pragma unroll
            for (int nt = 0; nt < 8; nt++) {
                int col = wn * 64 + nt * 8 + gid;
                bf[nt][0] = __float_as_uint(Bs[cur][(kk + tig) * BPAD + col]);
                bf[nt][1] = __float_as_uint(Bs[cur][(kk + tig + 4) * BPAD + col]);
            }
#pragma unroll
            for (int mt = 0; mt < 2; mt++)
#pragma unroll
                for (int nt = 0; nt < 8; nt++) {
                    asm volatile(
                        "mma.sync.aligned.m16n8k8.row.col.f32.tf32.tf32.f32 "
                        "{%0,%1,%2,%3}, {%4,%5,%6,%7}, {%8,%9}, {%0,%1,%2,%3};"
                        : "+f"(acc[mt][nt][0]), "+f"(acc[mt][nt][1]),
                          "+f"(acc[mt][nt][2]), "+f"(acc[mt][nt][3])
                        : "r"(af[mt][0]), "r"(af[mt][1]), "r"(af[mt][2]), "r"(af[mt][3]),
                          "r"(bf[nt][0]), "r"(bf[nt][1]));
                }
        }
        if (has_next) {
            int nb = cur ^ 1;
            float* p = &As[nb][am0 * APAD + ak0];
            p[0] = __uint_as_float(f2tf32(ra0.x)); p[1] = __uint_as_float(f2tf32(ra0.y));
            p[2] = __uint_as_float(f2tf32(ra0.z)); p[3] = __uint_as_float(f2tf32(ra0.w));
            p = &As[nb][am1 * APAD + ak1];
            p[0] = __uint_as_float(f2tf32(ra1.x)); p[1] = __uint_as_float(f2tf32(ra1.y));
            p[2] = __uint_as_float(f2tf32(ra1.z)); p[3] = __uint_as_float(f2tf32(ra1.w));
            p = &Bs[nb][bk0 * BPAD + bc0];
            p[0] = __uint_as_float(f2tf32(rb0.x)); p[1] = __uint_as_float(f2tf32(rb0.y));
            p[2] = __uint_as_float(f2tf32(rb0.z)); p[3] = __uint_as_float(f2tf32(rb0.w));
            p = &Bs[nb][bk1 * BPAD + bc1];
            p[0] = __uint_as_float(f2tf32(rb1.x)); p[1] = __uint_as_float(f2tf32(rb1.y));
            p[2] = __uint_as_float(f2tf32(rb1.z)); p[3] = __uint_as_float(f2tf32(rb1.w));
            __syncthreads();
            cur = nb;
        }
    }

    // ---------------- store C ----------------
#pragma unroll
    for (int mt = 0; mt < 2; mt++) {
#pragma unroll
        for (int nt = 0; nt < 8; nt++) {
            int col = bn + wn * 64 + nt * 8 + 2 * tig;
            if (col >= N) continue;
            int row0 = bm + wm * 32 + mt * 16 + gid;
            if (row0 < M)
                *(float2*)&C[(size_t)row0 * N + col] =
                    make_float2(acc[mt][nt][0], acc[mt][nt][1]);
            if (row0 + 8 < M)
                *(float2*)&C[(size_t)(row0 + 8) * N + col] =
                    make_float2(acc[mt][nt][2], acc[mt][nt][3]);
        }
    }

    // ------------- fused attention-logit epilogue -------------
    int wcb = bn + wn * 64;
    if (wcb < N) {
        int hd = wcb / C_head;
        float psrc[2][2] = {{0.f, 0.f}, {0.f, 0.f}};
        float pdst[2][2] = {{0.f, 0.f}, {0.f, 0.f}};
#pragma unroll
        for (int nt = 0; nt < 8; nt++) {
            int col = wcb + nt * 8 + 2 * tig;
            if (col >= N) continue;
            int cih = col - hd * C_head;
            float a0s = asrc[hd * C_head + cih], a1s = asrc[hd * C_head + cih + 1];
            float a0d = adst[hd * C_head + cih], a1d = adst[hd * C_head + cih + 1];
#pragma unroll
            for (int mt = 0; mt < 2; mt++) {
                psrc[mt][0] += acc[mt][nt][0] * a0s + acc[mt][nt][1] * a1s;
                pdst[mt][0] += acc[mt][nt][0] * a0d + acc[mt][nt][1] * a1d;
                psrc[mt][1] += acc[mt][nt][2] * a0s + acc[mt][nt][3] * a1s;
                pdst[mt][1] += acc[mt][nt][2] * a0d + acc[mt][nt][3] * a1d;
            }
        }
#pragma unroll
        for (int o = 1; o < 4; o <<= 1) {
#pragma unroll
            for (int mt = 0; mt < 2; mt++) {
#pragma unroll
                for (int hf = 0; hf < 2; hf++) {
                    psrc[mt][hf] += __shfl_xor_sync(0xFFFFFFFFu, psrc[mt][hf], o);
                    pdst[mt][hf] += __shfl_xor_sync(0xFFFFFFFFu, pdst[mt][hf], o);
                }
            }
        }
        if (tig == 0) {
#pragma unroll
            for (int mt = 0; mt < 2; mt++) {
#pragma unroll
                for (int hf = 0; hf < 2; hf++) {
                    int row = bm + wm * 32 + mt * 16 + gid + hf * 8;
                    if (row < M) {
                        g_ssrc[row * H + hd] = psrc[mt][hf];
                        g_sdst[row * H + hd] = pdst[mt][hf];
                    }
                }
            }
        }
    }
}

// =====================================================================
// Warp-per-node GAT propagate (H=4, C=64): 4x unrolled aggregation (MLP=8)
// =====================================================================
__global__ __launch_bounds__(256) void gat_warp4(
    const float* __restrict__ h, const float* __restrict__ bias,
    float* __restrict__ out, int n, int do_relu) {
    __shared__ float sw[8][128];

    int wid = threadIdx.x >> 5, lane = threadIdx.x & 31;
    int node = blockIdx.x * 8 + wid;
    if (node >= n) return;
    int e0 = g_rowptr[node], e1 = g_rowptr[node + 1];
    float4 sd = *(const float4*)&g_sdst[node * 4];
    int hd = lane >> 3;

    float4 m4 = make_float4(NEG_INF, NEG_INF, NEG_INF, NEG_INF);
    float4 s4 = make_float4(0.f, 0.f, 0.f, 0.f);
    float4 acc0 = make_float4(0.f, 0.f, 0.f, 0.f);
    float4 acc1 = make_float4(0.f, 0.f, 0.f, 0.f);

    for (int c0 = e0; c0 < e1; c0 += 32) {
        int cs = min(32, e1 - c0);
        int src = 0;
        float4 lg = make_float4(NEG_INF, NEG_INF, NEG_INF, NEG_INF);
        if (lane < cs) {
            src = g_csr_src[c0 + lane];
            float4 ss = *(const float4*)&g_ssrc[src * 4];
            lg.x = ss.x + sd.x; lg.x = lg.x >= 0.f ? lg.x : 0.2f * lg.x;
            lg.y = ss.y + sd.y; lg.y = lg.y >= 0.f ? lg.y : 0.2f * lg.y;
            lg.z = ss.z + sd.z; lg.z = lg.z >= 0.f ? lg.z : 0.2f * lg.z;
            lg.w = ss.w + sd.w; lg.w = lg.w >= 0.f ? lg.w : 0.2f * lg.w;
        }
        float4 cm = lg;
#pragma unroll
        for (int o = 16; o; o >>= 1) {
            cm.x = fmaxf(cm.x, __shfl_xor_sync(0xFFFFFFFFu, cm.x, o));
            cm.y = fmaxf(cm.y, __shfl_xor_sync(0xFFFFFFFFu, cm.y, o));
            cm.z = fmaxf(cm.z, __shfl_xor_sync(0xFFFFFFFFu, cm.z, o));
            cm.w = fmaxf(cm.w, __shfl_xor_sync(0xFFFFFFFFu, cm.w, o));
        }
        float4 mnew = make_float4(fmaxf(m4.x, cm.x), fmaxf(m4.y, cm.y),
                                  fmaxf(m4.z, cm.z), fmaxf(m4.w, cm.w));
        float4 f = make_float4(__expf(m4.x - mnew.x), __expf(m4.y - mnew.y),
                               __expf(m4.z - mnew.z), __expf(m4.w - mnew.w));
        float fh = pick4(f, hd);
        acc0.x *= fh; acc0.y *= fh; acc0.z *= fh; acc0.w *= fh;
        acc1.x *= fh; acc1.y *= fh; acc1.z *= fh; acc1.w *= fh;
        s4.x *= f.x; s4.y *= f.y; s4.z *= f.z; s4.w *= f.w;
        m4 = mnew;
        float4 w = make_float4(0.f, 0.f, 0.f, 0.f);
        if (lane < cs) {
            w.x = __expf(lg.x - m4.x); w.y = __expf(lg.y - m4.y);
            w.z = __expf(lg.z - m4.z); w.w = __expf(lg.w - m4.w);
        }
        float4 ws = w;
#pragma unroll
        for (int o = 16; o; o >>= 1) {
            ws.x += __shfl_xor_sync(0xFFFFFFFFu, ws.x, o);
            ws.y += __shfl_xor_sync(0xFFFFFFFFu, ws.y, o);
            ws.z += __shfl_xor_sync(0xFFFFFFFFu, ws.z, o);
            ws.w += __shfl_xor_sync(0xFFFFFFFFu, ws.w, o);
        }
        s4.x += ws.x; s4.y += ws.y; s4.z += ws.z; s4.w += ws.w;
        *(float4*)&sw[wid][lane * 4] = w;
        __syncwarp();

        // ---- aggregation, 4x unrolled: 8 LDG.128 in flight ----
        int e = 0;
        for (; e + 4 <= cs; e += 4) {
            int se0 = __shfl_sync(0xFFFFFFFFu, src, e);
            int se1 = __shfl_sync(0xFFFFFFFFu, src, e + 1);
            int se2 = __shfl_sync(0xFFFFFFFFu, src, e + 2);
            int se3 = __shfl_sync(0xFFFFFFFFu, src, e + 3);
            float w0 = sw[wid][(e + 0) * 4 + hd];
            float w1 = sw[wid][(e + 1) * 4 + hd];
            float w2 = sw[wid][(e + 2) * 4 + hd];
            float w3 = sw[wid][(e + 3) * 4 + hd];
            const float4* h0 = (const float4*)(h + (size_t)se0 * 256);
            const float4* h1 = (const float4*)(h + (size_t)se1 * 256);
            const float4* h2 = (const float4*)(h + (size_t)se2 * 256);
            const float4* h3 = (const float4*)(h + (size_t)se3 * 256);
            float4 a0 = h0[2 * lane], b0 = h0[2 * lane + 1];
            float4 a1 = h1[2 * lane], b1 = h1[2 * lane + 1];
            float4 a2 = h2[2 * lane], b2 = h2[2 * lane + 1];
            float4 a3 = h3[2 * lane], b3 = h3[2 * lane + 1];
            acc0.x += w0 * a0.x + w1 * a1.x + w2 * a2.x + w3 * a3.x;
            acc0.y += w0 * a0.y + w1 * a1.y + w2 * a2.y + w3 * a3.y;
            acc0.z += w0 * a0.z + w1 * a1.z + w2 * a2.z + w3 * a3.z;
            acc0.w += w0 * a0.w + w1 * a1.w + w2 * a2.w + w3 * a3.w;
            acc1.x += w0 * b0.x + w1 * b1.x + w2 * b2.x + w3 * b3.x;
            acc1.y += w0 * b0.y + w1 * b1.y + w2 * b2.y + w3 * b3.y;
            acc1.z += w0 * b0.z + w1 * b1.z + w2 * b2.z + w3 * b3.z;
            acc1.w += w0 * b0.w + w1 * b1.w + w2 * b2.w + w3 * b3.w;
        }
        for (; e < cs; e++) {
            int se = __shfl_sync(0xFFFFFFFFu, src, e);
            float we = sw[wid][e * 4 + hd];
            const float4* hp = (const float4*)(h + (size_t)se * 256);
            float4 v0 = hp[2 * lane], v1 = hp[2 * lane + 1];
            acc0.x += we * v0.x; acc0.y += we * v0.y;
            acc0.z += we * v0.z; acc0.w += we * v0.w;
            acc1.x += we * v1.x; acc1.y += we * v1.y;
            acc1.z += we * v1.z; acc1.w += we * v1.w;
        }
        __syncwarp();
    }
    float inv = 1.f / pick4(s4, hd);
    float4 b0 = *(const float4*)&bias[lane * 8];
    float4 b1 = *(const float4*)&bias[lane * 8 + 4];
    float4 o0, o1;
    o0.x = acc0.x * inv + b0.x; o0.y = acc0.y * inv + b0.y;
    o0.z = acc0.z * inv + b0.z; o0.w = acc0.w * inv + b0.w;
    o1.x = acc1.x * inv + b1.x; o1.y = acc1.y * inv + b1.y;
    o1.z = acc1.z * inv + b1.z; o1.w = acc1.w * inv + b1.w;
    if (do_relu) {
        o0.x = fmaxf(o0.x, 0.f); o0.y = fmaxf(o0.y, 0.f);
        o0.z = fmaxf(o0.z, 0.f); o0.w = fmaxf(o0.w, 0.f);
        o1.x = fmaxf(o1.x, 0.f); o1.y = fmaxf(o1.y, 0.f);
        o1.z = fmaxf(o1.z, 0.f); o1.w = fmaxf(o1.w, 0.f);
    }
    *(float4*)&out[(size_t)node * 256 + lane * 8] = o0;
    *(float4*)&out[(size_t)node * 256 + lane * 8 + 4] = o1;
}

// =====================================================================
// Fused GAT propagate (H=1, C=32): warp per dst node, 4x unrolled
// =====================================================================
__global__ void gat_fused1(const float* __restrict__ h, const float* __restrict__ bias,
                           float* __restrict__ out, int n) {
    int w = (blockIdx.x * blockDim.x + threadIdx.x) >> 5;
    int lane = threadIdx.x & 31;
    if (w >= n) return;
    int node = w;
    int e0 = g_rowptr[node], e1 = g_rowptr[node + 1];
    float sdst = g_sdst[node];
    float m = NEG_INF, s = 0.f, acc = 0.f;
    for (int c0 = e0; c0 < e1; c0 += 32) {
        int cs = min(32, e1 - c0);
        int src = (lane < cs) ? g_csr_src[c0 + lane] : 0;
        float v = NEG_INF;
        if (lane < cs) {
            v = g_ssrc[src] + sdst;
            v = v >= 0.f ? v : 0.2f * v;
        }
        float cm = v;
#pragma unroll
        for (int o = 16; o; o >>= 1) cm = fmaxf(cm, __shfl_xor_sync(0xFFFFFFFFu, cm, o));
        float mnew = fmaxf(m, cm);
        float f = __expf(m - mnew);
        acc *= f; s *= f; m = mnew;
        float wv = (lane < cs) ? __expf(v - m) : 0.f;
        float ps = wv;
#pragma unroll
        for (int o = 16; o; o >>= 1) ps += __shfl_xor_sync(0xFFFFFFFFu, ps, o);
        s += ps;
        int e = 0;
        for (; e + 4 <= cs; e += 4) {
            float w0 = __shfl_sync(0xFFFFFFFFu, wv, e);
            float w1 = __shfl_sync(0xFFFFFFFFu, wv, e + 1);
            float w2 = __shfl_sync(0xFFFFFFFFu, wv, e + 2);
            float w3 = __shfl_sync(0xFFFFFFFFu, wv, e + 3);
            int s0 = __shfl_sync(0xFFFFFFFFu, src, e);
            int s1 = __shfl_sync(0xFFFFFFFFu, src, e + 1);
            int s2 = __shfl_sync(0xFFFFFFFFu, src, e + 2);
            int s3 = __shfl_sync(0xFFFFFFFFu, src, e + 3);
            float v0 = h[(size_t)s0 * 32 + lane];
            float v1 = h[(size_t)s1 * 32 + lane];
            float v2 = h[(size_t)s2 * 32 + lane];
            float v3 = h[(size_t)s3 * 32 + lane];
            acc += w0 * v0 + w1 * v1 + w2 * v2 + w3 * v3;
        }
        for (; e < cs; e++) {
            float we = __shfl_sync(0xFFFFFFFFu, wv, e);
            int se = __shfl_sync(0xFFFFFFFFu, src, e);
            acc += we * h[(size_t)se * 32 + lane];
        }
    }
    out[(size_t)node * 32 + lane] = acc / s + bias[lane];
}

extern "C" void kernel_launch(void* const* d_in, const int* in_sizes, int n_in,
                              void* d_out, int out_size) {
    const float* x      = (const float*)d_in[0];
    const int*   ei     = (const int*)d_in[1];
    const float* W1     = (const float*)d_in[2];
    const float* a_src1 = (const float*)d_in[3];
    const float* a_dst1 = (const float*)d_in[4];
    const float* b1     = (const float*)d_in[5];
    const float* W2     = (const float*)d_in[6];
    const float* a_src2 = (const float*)d_in[7];
    const float* a_dst2 = (const float*)d_in[8];
    const float* b2     = (const float*)d_in[9];
    const float* W3     = (const float*)d_in[10];
    const float* a_src3 = (const float*)d_in[11];
    const float* a_dst3 = (const float*)d_in[12];
    const float* b3     = (const float*)d_in[13];
    float* out = (float*)d_out;

    int n = in_sizes[0] / 3;
    int E = in_sizes[1] / 2;
    int Etot = E + n;

    float *gA, *gB;
    cudaGetSymbolAddress((void**)&gA, g_A);
    cudaGetSymbolAddress((void**)&gB, g_B);

    int nb = (n + 255) / 256;
    int nw8 = (n + 7) / 8;
    dim3 g2((n + 127) / 128, 2);
    dim3 g3((n + 127) / 128, 1);

    // ---------------- CSR build ----------------
    csr_count<<<(E + 255) / 256, 256>>>(ei, E);
    scan_part<<<nb, 256>>>(n);
    scan_top<<<1, 32>>>(nb);
    scan_fin<<<nb, 256>>>(n);
    csr_fill<<<(Etot + 255) / 256, 256>>>(ei, E, Etot);

    // ---------------- Layer 1 ----------------
    gemm_l1_attn<<<n, 256>>>(x, W1, a_src1, a_dst1, gB, n);
    gat_warp4<<<nw8, 256>>>(gB, b1, gA, n, 1);

    // ---------------- Layer 2 ----------------
    mma_gemm<<<g2, 256>>>(gA, W2, gB, n, 256, 256, a_src2, a_dst2, 64, 4);
    gat_warp4<<<nw8, 256>>>(gB, b2, gA, n, 1);

    // ---------------- Layer 3 ----------------
    mma_gemm<<<g3, 256>>>(gA, W3, gB, n, 32, 256, a_src3, a_dst3, 32, 1);
    gat_fused1<<<(n * 32 + 255) / 256, 256>>>(gB, b3, out, n);
}

// round 10
// speedup vs baseline: 1.1192x; 1.1192x over previous
#include <cuda_runtime.h>
#include <cuda_fp16.h>

#define NMAX 50000
#define EMAXE 400000
#define ETOTMAX (EMAXE + NMAX)
#define NEG_INF __int_as_float(0xff800000)

// Scratch (static device globals — allocation-free)
__device__ float g_A[NMAX * 256];       // feature buffer (fp32, GEMM input)
__device__ float g_B[NMAX * 256];       // fp32 h (layer 3 only)
__device__ uint4 g_Bh4[NMAX * 32];      // fp16 h for layers 1-2 (16B-aligned)
__device__ float g_ssrc[NMAX * 4];      // per-node src attention logits [N,H]
__device__ float g_sdst[NMAX * 4];      // per-node dst attention logits [N,H]
__device__ int   g_csr_src[ETOTMAX];    // CSR: src ids grouped by dst
__device__ int   g_rowptr[NMAX + 1];    // CSR row pointers
__device__ int   g_wptr[NMAX];          // counts / write cursors (0 at start of every run)
__device__ int   g_blksum[260];         // scan partials

__device__ __forceinline__ unsigned f2tf32(float f) {
    unsigned u;
    asm("cvt.rna.tf32.f32 %0, %1;" : "=r"(u) : "f"(f));
    return u;
}

__device__ __forceinline__ float pick4(float4 v, int i) {
    float ab = (i & 1) ? v.y : v.x;
    float cd = (i & 1) ? v.w : v.z;
    return (i & 2) ? cd : ab;
}

// ============================ CSR construction ============================
__global__ void csr_count(const int* __restrict__ ei, int E) {
    int e = blockIdx.x * blockDim.x + threadIdx.x;
    if (e < E) atomicAdd(&g_wptr[ei[E + e]], 1);
}

__global__ void scan_part(int n) {
    __shared__ int ws[8];
    int i = blockIdx.x * 256 + threadIdx.x;
    int lane = threadIdx.x & 31, warp = threadIdx.x >> 5;
    int v = (i < n) ? g_wptr[i] + 1 : 0;
#pragma unroll
    for (int o = 16; o; o >>= 1) v += __shfl_xor_sync(0xFFFFFFFFu, v, o);
    if (!lane) ws[warp] = v;
    __syncthreads();
    if (threadIdx.x < 8) {
        int t = ws[threadIdx.x];
#pragma unroll
        for (int o = 4; o; o >>= 1) t += __shfl_xor_sync(0xFFu, t, o, 8);
        if (!threadIdx.x) g_blksum[blockIdx.x] = t;
    }
}

__global__ void scan_top(int nb) {
    int lane = threadIdx.x;
    int carry = 0;
    for (int base = 0; base < nb; base += 32) {
        int idx = base + lane;
        int v = (idx < nb) ? g_blksum[idx] : 0;
        int orig = v;
#pragma unroll
        for (int o = 1; o < 32; o <<= 1) {
            int t = __shfl_up_sync(0xFFFFFFFFu, v, o);
            if (lane >= o) v += t;
        }
        if (idx < nb) g_blksum[idx] = carry + v - orig;  // exclusive
        carry += __shfl_sync(0xFFFFFFFFu, v, 31);
    }
}

__global__ void scan_fin(int n) {
    __shared__ int wsum[8];
    int tid = threadIdx.x, i = blockIdx.x * 256 + tid;
    int lane = tid & 31, warp = tid >> 5;
    int v = (i < n) ? g_wptr[i] + 1 : 0;
    int x = v;
#pragma unroll
    for (int o = 1; o < 32; o <<= 1) {
        int t = __shfl_up_sync(0xFFFFFFFFu, x, o);
        if (lane >= o) x += t;
    }
    if (lane == 31) wsum[warp] = x;
    __syncthreads();
    if (warp == 0 && lane < 8) {
        int s = wsum[lane];
#pragma unroll
        for (int o = 1; o < 8; o <<= 1) {
            int t = __shfl_up_sync(0xFFu, s, o, 8);
            if (lane >= o) s += t;
        }
        wsum[lane] = s;
    }
    __syncthreads();
    int woff = warp ? wsum[warp - 1] : 0;
    int incl = x + woff;
    int off = g_blksum[blockIdx.x];
    if (i < n) { g_rowptr[i] = off + incl - v; g_wptr[i] = 0; }
    if (i == n - 1) g_rowptr[n] = off + incl;
}

__global__ void csr_fill(const int* __restrict__ ei, int E, int Etot) {
    int e = blockIdx.x * blockDim.x + threadIdx.x;
    if (e >= Etot) return;
    int s, d;
    if (e < E) { s = ei[e]; d = ei[E + e]; } else { s = d = e - E; }
    int pos = atomicAdd(&g_wptr[d], 1);
    g_csr_src[g_rowptr[d] + pos] = s;
}

// ============== layer 1 GEMM + fused attention logits (fp16 h out) ==============
__global__ void gemm_l1_attn(const float* __restrict__ x, const float* __restrict__ W,
                             const float* __restrict__ asrc, const float* __restrict__ adst,
                             __half* __restrict__ out, int n) {
    __shared__ float xs[3];
    __shared__ float r1[8], r2[8];
    int node = blockIdx.x;
    if (node >= n) return;
    int tid = threadIdx.x;
    if (tid < 3) xs[tid] = x[node * 3 + tid];
    if (tid == 32) g_wptr[node] = 0;  // cursor reset for next replay
    __syncthreads();
    float acc = xs[0] * W[tid] + xs[1] * W[256 + tid] + xs[2] * W[512 + tid];
    out[(size_t)node * 256 + tid] = __float2half(acc);
    float p1 = acc * asrc[tid];
    float p2 = acc * adst[tid];
#pragma unroll
    for (int o = 16; o; o >>= 1) {
        p1 += __shfl_xor_sync(0xFFFFFFFFu, p1, o);
        p2 += __shfl_xor_sync(0xFFFFFFFFu, p2, o);
    }
    int warp = tid >> 5, lane = tid & 31;
    if (!lane) { r1[warp] = p1; r2[warp] = p2; }
    __syncthreads();
    if (tid < 4) {
        g_ssrc[node * 4 + tid] = r1[tid * 2] + r1[tid * 2 + 1];
        g_sdst[node * 4 + tid] = r2[tid * 2] + r2[tid * 2 + 1];
    }
}

// =====================================================================
// tf32 tensor-core GEMM, double-buffered smem, fused attn-logit epilogue.
// out_half: C stored as fp16 (layers 1-2 h) or fp32 (layer 3 h).
// =====================================================================
#define APAD 20
#define BPAD 136

__global__ __launch_bounds__(256) void mma_gemm(
    const float* __restrict__ A, const float* __restrict__ Bw,
    float* __restrict__ C, __half* __restrict__ Ch, int out_half,
    int M, int N, int K,
    const float* __restrict__ asrc, const float* __restrict__ adst,
    int C_head, int H) {
    __shared__ float As[2][128 * APAD];
    __shared__ float Bs[2][16 * BPAD];

    int tid = threadIdx.x;
    int warp = tid >> 5, lane = tid & 31;
    int gid = lane >> 2, tig = lane & 3;
    int wm = warp & 3, wn = warp >> 2;
    int bm = blockIdx.x * 128, bn = blockIdx.y * 128;

    int am0 = (tid * 2) >> 2, ak0 = ((tid * 2) & 3) * 4;
    int am1 = (tid * 2 + 1) >> 2, ak1 = ((tid * 2 + 1) & 3) * 4;
    int bk0 = (tid * 2) >> 5, bc0 = ((tid * 2) & 31) * 4;
    int bk1 = (tid * 2 + 1) >> 5, bc1 = ((tid * 2 + 1) & 31) * 4;

    float acc[2][8][4];
#pragma unroll
    for (int i = 0; i < 2; i++)
#pragma unroll
        for (int j = 0; j < 8; j++)
#pragma unroll
            for (int r = 0; r < 4; r++) acc[i][j][r] = 0.f;

    float4 ra0, ra1, rb0, rb1;
    {
        ra0 = make_float4(0.f, 0.f, 0.f, 0.f);
        ra1 = ra0; rb0 = ra0; rb1 = ra0;
        if (bm + am0 < M) ra0 = *(const float4*)&A[(size_t)(bm + am0) * K + ak0];
        if (bm + am1 < M) ra1 = *(const float4*)&A[(size_t)(bm + am1) * K + ak1];
        if (bn + bc0 < N) rb0 = *(const float4*)&Bw[(size_t)bk0 * N + bn + bc0];
        if (bn + bc1 < N) rb1 = *(const float4*)&Bw[(size_t)bk1 * N + bn + bc1];
    }
    {
        float* p = &As[0][am0 * APAD + ak0];
        p[0] = __uint_as_float(f2tf32(ra0.x)); p[1] = __uint_as_float(f2tf32(ra0.y));
        p[2] = __uint_as_float(f2tf32(ra0.z)); p[3] = __uint_as_float(f2tf32(ra0.w));
        p = &As[0][am1 * APAD + ak1];
        p[0] = __uint_as_float(f2tf32(ra1.x)); p[1] = __uint_as_float(f2tf32(ra1.y));
        p[2] = __uint_as_float(f2tf32(ra1.z)); p[3] = __uint_as_float(f2tf32(ra1.w));
        p = &Bs[0][bk0 * BPAD + bc0];
        p[0] = __uint_as_float(f2tf32(rb0.x)); p[1] = __uint_as_float(f2tf32(rb0.y));
        p[2] = __uint_as_float(f2tf32(rb0.z)); p[3] = __uint_as_float(f2tf32(rb0.w));
        p = &Bs[0][bk1 * BPAD + bc1];
        p[0] = __uint_as_float(f2tf32(rb1.x)); p[1] = __uint_as_float(f2tf32(rb1.y));
        p[2] = __uint_as_float(f2tf32(rb1.z)); p[3] = __uint_as_float(f2tf32(rb1.w));
    }
    __syncthreads();

    int cur = 0;
    for (int k0 = 0; k0 < K; k0 += 16) {
        bool has_next = (k0 + 16) < K;
        if (has_next) {
            int kn = k0 + 16;
            ra0 = make_float4(0.f, 0.f, 0.f, 0.f);
            ra1 = ra0; rb0 = ra0; rb1 = ra0;
            if (bm + am0 < M) ra0 = *(const float4*)&A[(size_t)(bm + am0) * K + kn + ak0];
            if (bm + am1 < M) ra1 = *(const float4*)&A[(size_t)(bm + am1) * K + kn + ak1];
            if (bn + bc0 < N) rb0 = *(const float4*)&Bw[(size_t)(kn + bk0) * N + bn + bc0];
            if (bn + bc1 < N) rb1 = *(const float4*)&Bw[(size_t)(kn + bk1) * N + bn + bc1];
        }
#pragma unroll
        for (int kk = 0; kk < 16; kk += 8) {
            unsigned af[2][4], bf[8][2];
#pragma unroll
            for (int mt = 0; mt < 2; mt++) {
                int row = wm * 32 + mt * 16 + gid;
                af[mt][0] = __float_as_uint(As[cur][row * APAD + kk + tig]);
                af[mt][1] = __float_as_uint(As[cur][(row + 8) * APAD + kk + tig]);
                af[mt][2] = __float_as_uint(As[cur][row * APAD + kk + tig + 4]);
                af[mt][3] = __float_as_uint(As[cur][(row + 8) * APAD + kk + tig + 4]);
            }
#pragma unroll
            for (int nt = 0; nt < 8; nt++) {
                int col = wn * 64 + nt * 8 + gid;
                bf[nt][0] = __float_as_uint(Bs[cur][(kk + tig) * BPAD + col]);
                bf[nt][1] = __float_as_uint(Bs[cur][(kk + tig + 4) * BPAD + col]);
            }
#pragma unroll
            for (int mt = 0; mt < 2; mt++)
#pragma unroll
                for (int nt = 0; nt < 8; nt++) {
                    asm volatile(
                        "mma.sync.aligned.m16n8k8.row.col.f32.tf32.tf32.f32 "
                        "{%0,%1,%2,%3}, {%4,%5,%6,%7}, {%8,%9}, {%0,%1,%2,%3};"
                        : "+f"(acc[mt][nt][0]), "+f"(acc[mt][nt][1]),
                          "+f"(acc[mt][nt][2]), "+f"(acc[mt][nt][3])
                        : "r"(af[mt][0]), "r"(af[mt][1]), "r"(af[mt][2]), "r"(af[mt][3]),
                          "r"(bf[nt][0]), "r"(bf[nt][1]));
                }
        }
        if (has_next) {
            int nb = cur ^ 1;
            float* p = &As[nb][am0 * APAD + ak0];
            p[0] = __uint_as_float(f2tf32(ra0.x)); p[1] = __uint_as_float(f2tf32(ra0.y));
            p[2] = __uint_as_float(f2tf32(ra0.z)); p[3] = __uint_as_float(f2tf32(ra0.w));
            p = &As[nb][am1 * APAD + ak1];
            p[0] = __uint_as_float(f2tf32(ra1.x)); p[1] = __uint_as_float(f2tf32(ra1.y));
            p[2] = __uint_as_float(f2tf32(ra1.z)); p[3] = __uint_as_float(f2tf32(ra1.w));
            p = &Bs[nb][bk0 * BPAD + bc0];
            p[0] = __uint_as_float(f2tf32(rb0.x)); p[1] = __uint_as_float(f2tf32(rb0.y));
            p[2] = __uint_as_float(f2tf32(rb0.z)); p[3] = __uint_as_float(f2tf32(rb0.w));
            p = &Bs[nb][bk1 * BPAD + bc1];
            p[0] = __uint_as_float(f2tf32(rb1.x)); p[1] = __uint_as_float(f2tf32(rb1.y));
            p[2] = __uint_as_float(f2tf32(rb1.z)); p[3] = __uint_as_float(f2tf32(rb1.w));
            __syncthreads();
            cur = nb;
        }
    }

    // ---------------- store C (fp16 or fp32) ----------------
#pragma unroll
    for (int mt = 0; mt < 2; mt++) {
#pragma unroll
        for (int nt = 0; nt < 8; nt++) {
            int col = bn + wn * 64 + nt * 8 + 2 * tig;
            if (col >= N) continue;
            int row0 = bm + wm * 32 + mt * 16 + gid;
            if (out_half) {
                if (row0 < M)
                    *(__half2*)&Ch[(size_t)row0 * N + col] =
                        __float22half2_rn(make_float2(acc[mt][nt][0], acc[mt][nt][1]));
                if (row0 + 8 < M)
                    *(__half2*)&Ch[(size_t)(row0 + 8) * N + col] =
                        __float22half2_rn(make_float2(acc[mt][nt][2], acc[mt][nt][3]));
            } else {
                if (row0 < M)
                    *(float2*)&C[(size_t)row0 * N + col] =
                        make_float2(acc[mt][nt][0], acc[mt][nt][1]);
                if (row0 + 8 < M)
                    *(float2*)&C[(size_t)(row0 + 8) * N + col] =
                        make_float2(acc[mt][nt][2], acc[mt][nt][3]);
            }
        }
    }

    // ------------- fused attention-logit epilogue (fp32 regs) -------------
    int wcb = bn + wn * 64;
    if (wcb < N) {
        int hd = wcb / C_head;
        float psrc[2][2] = {{0.f, 0.f}, {0.f, 0.f}};
        float pdst[2][2] = {{0.f, 0.f}, {0.f, 0.f}};
#pragma unroll
        for (int nt = 0; nt < 8; nt++) {
            int col = wcb + nt * 8 + 2 * tig;
            if (col >= N) continue;
            int cih = col - hd * C_head;
            float a0s = asrc[hd * C_head + cih], a1s = asrc[hd * C_head + cih + 1];
            float a0d = adst[hd * C_head + cih], a1d = adst[hd * C_head + cih + 1];
#pragma unroll
            for (int mt = 0; mt < 2; mt++) {
                psrc[mt][0] += acc[mt][nt][0] * a0s + acc[mt][nt][1] * a1s;
                pdst[mt][0] += acc[mt][nt][0] * a0d + acc[mt][nt][1] * a1d;
                psrc[mt][1] += acc[mt][nt][2] * a0s + acc[mt][nt][3] * a1s;
                pdst[mt][1] += acc[mt][nt][2] * a0d + acc[mt][nt][3] * a1d;
            }
        }
#pragma unroll
        for (int o = 1; o < 4; o <<= 1) {
#pragma unroll
            for (int mt = 0; mt < 2; mt++) {
#pragma unroll
                for (int hf = 0; hf < 2; hf++) {
                    psrc[mt][hf] += __shfl_xor_sync(0xFFFFFFFFu, psrc[mt][hf], o);
                    pdst[mt][hf] += __shfl_xor_sync(0xFFFFFFFFu, pdst[mt][hf], o);
                }
            }
        }
        if (tig == 0) {
#pragma unroll
            for (int mt = 0; mt < 2; mt++) {
#pragma unroll
                for (int hf = 0; hf < 2; hf++) {
                    int row = bm + wm * 32 + mt * 16 + gid + hf * 8;
                    if (row < M) {
                        g_ssrc[row * H + hd] = psrc[mt][hf];
                        g_sdst[row * H + hd] = pdst[mt][hf];
                    }
                }
            }
        }
    }
}

// =====================================================================
// Warp-per-node GAT propagate (H=4, C=64), fp16 gather: 1 LDG.128/lane/edge
// =====================================================================
__global__ __launch_bounds__(256) void gat_warp4(
    const __half* __restrict__ h, const float* __restrict__ bias,
    float* __restrict__ out, int n, int do_relu) {
    __shared__ float sw[8][128];

    int wid = threadIdx.x >> 5, lane = threadIdx.x & 31;
    int node = blockIdx.x * 8 + wid;
    if (node >= n) return;
    int e0 = g_rowptr[node], e1 = g_rowptr[node + 1];
    float4 sd = *(const float4*)&g_sdst[node * 4];
    int hd = lane >> 3;

    float4 m4 = make_float4(NEG_INF, NEG_INF, NEG_INF, NEG_INF);
    float4 s4 = make_float4(0.f, 0.f, 0.f, 0.f);
    float4 acc0 = make_float4(0.f, 0.f, 0.f, 0.f);
    float4 acc1 = make_float4(0.f, 0.f, 0.f, 0.f);

    for (int c0 = e0; c0 < e1; c0 += 32) {
        int cs = min(32, e1 - c0);
        int src = 0;
        float4 lg = make_float4(NEG_INF, NEG_INF, NEG_INF, NEG_INF);
        if (lane < cs) {
            src = g_csr_src[c0 + lane];
            float4 ss = *(const float4*)&g_ssrc[src * 4];
            lg.x = ss.x + sd.x; lg.x = lg.x >= 0.f ? lg.x : 0.2f * lg.x;
            lg.y = ss.y + sd.y; lg.y = lg.y >= 0.f ? lg.y : 0.2f * lg.y;
            lg.z = ss.z + sd.z; lg.z = lg.z >= 0.f ? lg.z : 0.2f * lg.z;
            lg.w = ss.w + sd.w; lg.w = lg.w >= 0.f ? lg.w : 0.2f * lg.w;
        }
        float4 cm = lg;
#pragma unroll
        for (int o = 16; o; o >>= 1) {
            cm.x = fmaxf(cm.x, __shfl_xor_sync(0xFFFFFFFFu, cm.x, o));
            cm.y = fmaxf(cm.y, __shfl_xor_sync(0xFFFFFFFFu, cm.y, o));
            cm.z = fmaxf(cm.z, __shfl_xor_sync(0xFFFFFFFFu, cm.z, o));
            cm.w = fmaxf(cm.w, __shfl_xor_sync(0xFFFFFFFFu, cm.w, o));
        }
        float4 mnew = make_float4(fmaxf(m4.x, cm.x), fmaxf(m4.y, cm.y),
                                  fmaxf(m4.z, cm.z), fmaxf(m4.w, cm.w));
        float4 f = make_float4(__expf(m4.x - mnew.x), __expf(m4.y - mnew.y),
                               __expf(m4.z - mnew.z), __expf(m4.w - mnew.w));
        float fh = pick4(f, hd);
        acc0.x *= fh; acc0.y *= fh; acc0.z *= fh; acc0.w *= fh;
        acc1.x *= fh; acc1.y *= fh; acc1.z *= fh; acc1.w *= fh;
        s4.x *= f.x; s4.y *= f.y; s4.z *= f.z; s4.w *= f.w;
        m4 = mnew;
        float4 w = make_float4(0.f, 0.f, 0.f, 0.f);
        if (lane < cs) {
            w.x = __expf(lg.x - m4.x); w.y = __expf(lg.y - m4.y);
            w.z = __expf(lg.z - m4.z); w.w = __expf(lg.w - m4.w);
        }
        float4 ws = w;
#pragma unroll
        for (int o = 16; o; o >>= 1) {
            ws.x += __shfl_xor_sync(0xFFFFFFFFu, ws.x, o);
            ws.y += __shfl_xor_sync(0xFFFFFFFFu, ws.y, o);
            ws.z += __shfl_xor_sync(0xFFFFFFFFu, ws.z, o);
            ws.w += __shfl_xor_sync(0xFFFFFFFFu, ws.w, o);
        }
        s4.x += ws.x; s4.y += ws.y; s4.z += ws.z; s4.w += ws.w;
        *(float4*)&sw[wid][lane * 4] = w;
        __syncwarp();

        // ---- aggregation: fp16 rows, 4x unrolled (4 LDG.128 in flight) ----
        int e = 0;
        for (; e + 4 <= cs; e += 4) {
            int se0 = __shfl_sync(0xFFFFFFFFu, src, e);
            int se1 = __shfl_sync(0xFFFFFFFFu, src, e + 1);
            int se2 = __shfl_sync(0xFFFFFFFFu, src, e + 2);
            int se3 = __shfl_sync(0xFFFFFFFFu, src, e + 3);
            float w0 = sw[wid][(e + 0) * 4 + hd];
            float w1 = sw[wid][(e + 1) * 4 + hd];
            float w2 = sw[wid][(e + 2) * 4 + hd];
            float w3 = sw[wid][(e + 3) * 4 + hd];
            uint4 u0 = ((const uint4*)(h + (size_t)se0 * 256))[lane];
            uint4 u1 = ((const uint4*)(h + (size_t)se1 * 256))[lane];
            uint4 u2 = ((const uint4*)(h + (size_t)se2 * 256))[lane];
            uint4 u3 = ((const uint4*)(h + (size_t)se3 * 256))[lane];
#define ACC_H8(u, wgt)                                                        \
            {                                                                 \
                float2 t0 = __half22float2(*(__half2*)&(u).x);                \
                float2 t1 = __half22float2(*(__half2*)&(u).y);                \
                float2 t2 = __half22float2(*(__half2*)&(u).z);                \
                float2 t3 = __half22float2(*(__half2*)&(u).w);                \
                acc0.x += (wgt) * t0.x; acc0.y += (wgt) * t0.y;               \
                acc0.z += (wgt) * t1.x; acc0.w += (wgt) * t1.y;               \
                acc1.x += (wgt) * t2.x; acc1.y += (wgt) * t2.y;               \
                acc1.z += (wgt) * t3.x; acc1.w += (wgt) * t3.y;               \
            }
            ACC_H8(u0, w0) ACC_H8(u1, w1) ACC_H8(u2, w2) ACC_H8(u3, w3)
        }
        for (; e < cs; e++) {
            int se = __shfl_sync(0xFFFFFFFFu, src, e);
            float we = sw[wid][e * 4 + hd];
            uint4 u = ((const uint4*)(h + (size_t)se * 256))[lane];
            ACC_H8(u, we)
        }
#undef ACC_H8
        __syncwarp();
    }
    float inv = 1.f / pick4(s4, hd);
    float4 b0 = *(const float4*)&bias[lane * 8];
    float4 b1 = *(const float4*)&bias[lane * 8 + 4];
    float4 o0, o1;
    o0.x = acc0.x * inv + b0.x; o0.y = acc0.y * inv + b0.y;
    o0.z = acc0.z * inv + b0.z; o0.w = acc0.w * inv + b0.w;
    o1.x = acc1.x * inv + b1.x; o1.y = acc1.y * inv + b1.y;
    o1.z = acc1.z * inv + b1.z; o1.w = acc1.w * inv + b1.w;
    if (do_relu) {
        o0.x = fmaxf(o0.x, 0.f); o0.y = fmaxf(o0.y, 0.f);
        o0.z = fmaxf(o0.z, 0.f); o0.w = fmaxf(o0.w, 0.f);
        o1.x = fmaxf(o1.x, 0.f); o1.y = fmaxf(o1.y, 0.f);
        o1.z = fmaxf(o1.z, 0.f); o1.w = fmaxf(o1.w, 0.f);
    }
    *(float4*)&out[(size_t)node * 256 + lane * 8] = o0;
    *(float4*)&out[(size_t)node * 256 + lane * 8 + 4] = o1;
}

// =====================================================================
// Fused GAT propagate (H=1, C=32): warp per dst node, fp32 h (final layer)
// =====================================================================
__global__ void gat_fused1(const float* __restrict__ h, const float* __restrict__ bias,
                           float* __restrict__ out, int n) {
    int w = (blockIdx.x * blockDim.x + threadIdx.x) >> 5;
    int lane = threadIdx.x & 31;
    if (w >= n) return;
    int node = w;
    int e0 = g_rowptr[node], e1 = g_rowptr[node + 1];
    float sdst = g_sdst[node];
    float m = NEG_INF, s = 0.f, acc = 0.f;
    for (int c0 = e0; c0 < e1; c0 += 32) {
        int cs = min(32, e1 - c0);
        int src = (lane < cs) ? g_csr_src[c0 + lane] : 0;
        float v = NEG_INF;
        if (lane < cs) {
            v = g_ssrc[src] + sdst;
            v = v >= 0.f ? v : 0.2f * v;
        }
        float cm = v;
#pragma unroll
        for (int o = 16; o; o >>= 1) cm = fmaxf(cm, __shfl_xor_sync(0xFFFFFFFFu, cm, o));
        float mnew = fmaxf(m, cm);
        float f = __expf(m - mnew);
        acc *= f; s *= f; m = mnew;
        float wv = (lane < cs) ? __expf(v - m) : 0.f;
        float ps = wv;
#pragma unroll
        for (int o = 16; o; o >>= 1) ps += __shfl_xor_sync(0xFFFFFFFFu, ps, o);
        s += ps;
        int e = 0;
        for (; e + 4 <= cs; e += 4) {
            float w0 = __shfl_sync(0xFFFFFFFFu, wv, e);
            float w1 = __shfl_sync(0xFFFFFFFFu, wv, e + 1);
            float w2 = __shfl_sync(0xFFFFFFFFu, wv, e + 2);
            float w3 = __shfl_sync(0xFFFFFFFFu, wv, e + 3);
            int s0 = __shfl_sync(0xFFFFFFFFu, src, e);
            int s1 = __shfl_sync(0xFFFFFFFFu, src, e + 1);
            int s2 = __shfl_sync(0xFFFFFFFFu, src, e + 2);
            int s3 = __shfl_sync(0xFFFFFFFFu, src, e + 3);
            float v0 = h[(size_t)s0 * 32 + lane];
            float v1 = h[(size_t)s1 * 32 + lane];
            float v2 = h[(size_t)s2 * 32 + lane];
            float v3 = h[(size_t)s3 * 32 + lane];
            acc += w0 * v0 + w1 * v1 + w2 * v2 + w3 * v3;
        }
        for (; e < cs; e++) {
            float we = __shfl_sync(0xFFFFFFFFu, wv, e);
            int se = __shfl_sync(0xFFFFFFFFu, src, e);
            acc += we * h[(size_t)se * 32 + lane];
        }
    }
    out[(size_t)node * 32 + lane] = acc / s + bias[lane];
}

extern "C" void kernel_launch(void* const* d_in, const int* in_sizes, int n_in,
                              void* d_out, int out_size) {
    const float* x      = (const float*)d_in[0];
    const int*   ei     = (const int*)d_in[1];
    const float* W1     = (const float*)d_in[2];
    const float* a_src1 = (const float*)d_in[3];
    const float* a_dst1 = (const float*)d_in[4];
    const float* b1     = (const float*)d_in[5];
    const float* W2     = (const float*)d_in[6];
    const float* a_src2 = (const float*)d_in[7];
    const float* a_dst2 = (const float*)d_in[8];
    const float* b2     = (const float*)d_in[9];
    const float* W3     = (const float*)d_in[10];
    const float* a_src3 = (const float*)d_in[11];
    const float* a_dst3 = (const float*)d_in[12];
    const float* b3     = (const float*)d_in[13];
    float* out = (float*)d_out;

    int n = in_sizes[0] / 3;
    int E = in_sizes[1] / 2;
    int Etot = E + n;

    float *gA, *gB;
    __half* gBh;
    cudaGetSymbolAddress((void**)&gA, g_A);
    cudaGetSymbolAddress((void**)&gB, g_B);
    cudaGetSymbolAddress((void**)&gBh, g_Bh4);

    int nb = (n + 255) / 256;
    int nw8 = (n + 7) / 8;
    dim3 g2((n + 127) / 128, 2);
    dim3 g3((n + 127) / 128, 1);

    // ---------------- CSR build ----------------
    csr_count<<<(E + 255) / 256, 256>>>(ei, E);
    scan_part<<<nb, 256>>>(n);
    scan_top<<<1, 32>>>(nb);
    scan_fin<<<nb, 256>>>(n);
    csr_fill<<<(Etot + 255) / 256, 256>>>(ei, E, Etot);

    // ---------------- Layer 1: fp16 h ----------------
    gemm_l1_attn<<<n, 256>>>(x, W1, a_src1, a_dst1, gBh, n);
    gat_warp4<<<nw8, 256>>>(gBh, b1, gA, n, 1);

    // ---------------- Layer 2: fp16 h ----------------
    mma_gemm<<<g2, 256>>>(gA, W2, nullptr, gBh, 1, n, 256, 256, a_src2, a_dst2, 64, 4);
    gat_warp4<<<nw8, 256>>>(gBh, b2, gA, n, 1);

    // ---------------- Layer 3: fp32 h (final precision) ----------------
    mma_gemm<<<g3, 256>>>(gA, W3, gB, nullptr, 0, n, 32, 256, a_src3, a_dst3, 32, 1);
    gat_fused1<<<(n * 32 + 255) / 256, 256>>>(gB, b3, out, n);
}

// round 12
// speedup vs baseline: 1.3077x; 1.1684x over previous
#include <cuda_runtime.h>
#include <cuda_fp16.h>

#define NMAX 50000
#define EMAXE 400000
#define ETOTMAX (EMAXE + NMAX)
#define NEG_INF __int_as_float(0xff800000)

// Scratch (static device globals — allocation-free)
__device__ uint4  g_Ah4[NMAX * 32];     // fp16 feature buffer (GEMM input / gat output)
__device__ uint4  g_Bh4[NMAX * 32];     // fp16 h (gat input, layers 1-2)
__device__ float  g_B[NMAX * 32];       // fp32 h (layer 3)
__device__ uint4  g_W2h4[256 * 32];     // W2^T fp16 [N=256][K=256]
__device__ uint4  g_W3h4[32 * 32];      // W3^T fp16 [N=32][K=256]
__device__ float  g_ssrc[NMAX * 4];     // per-node src attention logits [N,H]
__device__ float  g_sdst[NMAX * 4];     // per-node dst attention logits [N,H]
__device__ int    g_csr_src[ETOTMAX];   // CSR: src ids grouped by dst
__device__ int    g_rowptr[NMAX + 1];   // CSR row pointers
__device__ int    g_wptr[NMAX];         // counts / write cursors (0 at start of every run)
__device__ int    g_blksum[260];        // scan partials

__device__ __forceinline__ float pick4(float4 v, int i) {
    float ab = (i & 1) ? v.y : v.x;
    float cd = (i & 1) ? v.w : v.z;
    return (i & 2) ? cd : ab;
}

// ============== weight convert: W[K][N] fp32 -> Wt[N][K] fp16 ==============
__global__ void w_cvt(const float* __restrict__ W, __half* __restrict__ Wt,
                      int K, int N) {
    __shared__ float t[32][33];
    int k0 = blockIdx.y * 32, n0 = blockIdx.x * 32;
    int tx = threadIdx.x, ty = threadIdx.y;  // 32 x 8
    for (int i = ty; i < 32; i += 8) {
        int k = k0 + i, n = n0 + tx;
        t[i][tx] = (k < K && n < N) ? W[(size_t)k * N + n] : 0.f;
    }
    __syncthreads();
    for (int i = ty; i < 32; i += 8) {
        int n = n0 + i, k = k0 + tx;
        if (n < N && k < K) Wt[(size_t)n * K + k] = __float2half(t[tx][i]);
    }
}

// ============================ CSR construction ============================
__global__ void csr_count(const int* __restrict__ ei, int E) {
    int e = blockIdx.x * blockDim.x + threadIdx.x;
    if (e < E) atomicAdd(&g_wptr[ei[E + e]], 1);
}

__global__ void scan_part(int n) {
    __shared__ int ws[8];
    int i = blockIdx.x * 256 + threadIdx.x;
    int lane = threadIdx.x & 31, warp = threadIdx.x >> 5;
    int v = (i < n) ? g_wptr[i] + 1 : 0;
#pragma unroll
    for (int o = 16; o; o >>= 1) v += __shfl_xor_sync(0xFFFFFFFFu, v, o);
    if (!lane) ws[warp] = v;
    __syncthreads();
    if (threadIdx.x < 8) {
        int t = ws[threadIdx.x];
#pragma unroll
        for (int o = 4; o; o >>= 1) t += __shfl_xor_sync(0xFFu, t, o, 8);
        if (!threadIdx.x) g_blksum[blockIdx.x] = t;
    }
}

__global__ void scan_top(int nb) {
    int lane = threadIdx.x;
    int carry = 0;
    for (int base = 0; base < nb; base += 32) {
        int idx = base + lane;
        int v = (idx < nb) ? g_blksum[idx] : 0;
        int orig = v;
#pragma unroll
        for (int o = 1; o < 32; o <<= 1) {
            int t = __shfl_up_sync(0xFFFFFFFFu, v, o);
            if (lane >= o) v += t;
        }
        if (idx < nb) g_blksum[idx] = carry + v - orig;  // exclusive
        carry += __shfl_sync(0xFFFFFFFFu, v, 31);
    }
}

__global__ void scan_fin(int n) {
    __shared__ int wsum[8];
    int tid = threadIdx.x, i = blockIdx.x * 256 + tid;
    int lane = tid & 31, warp = tid >> 5;
    int v = (i < n) ? g_wptr[i] + 1 : 0;
    int x = v;
#pragma unroll
    for (int o = 1; o < 32; o <<= 1) {
        int t = __shfl_up_sync(0xFFFFFFFFu, x, o);
        if (lane >= o) x += t;
    }
    if (lane == 31) wsum[warp] = x;
    __syncthreads();
    if (warp == 0 && lane < 8) {
        int s = wsum[lane];
#pragma unroll
        for (int o = 1; o < 8; o <<= 1) {
            int t = __shfl_up_sync(0xFFu, s, o, 8);
            if (lane >= o) s += t;
        }
        wsum[lane] = s;
    }
    __syncthreads();
    int woff = warp ? wsum[warp - 1] : 0;
    int incl = x + woff;
    int off = g_blksum[blockIdx.x];
    if (i < n) { g_rowptr[i] = off + incl - v; g_wptr[i] = 0; }
    if (i == n - 1) g_rowptr[n] = off + incl;
}

__global__ void csr_fill(const int* __restrict__ ei, int E, int Etot) {
    int e = blockIdx.x * blockDim.x + threadIdx.x;
    if (e >= Etot) return;
    int s, d;
    if (e < E) { s = ei[e]; d = ei[E + e]; } else { s = d = e - E; }
    int pos = atomicAdd(&g_wptr[d], 1);
    g_csr_src[g_rowptr[d] + pos] = s;
}

// ============== layer 1 GEMM + fused attention logits (fp16 h out) ==============
__global__ void gemm_l1_attn(const float* __restrict__ x, const float* __restrict__ W,
                             const float* __restrict__ asrc, const float* __restrict__ adst,
                             __half* __restrict__ out, int n) {
    __shared__ float xs[3];
    __shared__ float r1[8], r2[8];
    int node = blockIdx.x;
    if (node >= n) return;
    int tid = threadIdx.x;
    if (tid < 3) xs[tid] = x[node * 3 + tid];
    if (tid == 32) g_wptr[node] = 0;  // cursor reset for next replay
    __syncthreads();
    float acc = xs[0] * W[tid] + xs[1] * W[256 + tid] + xs[2] * W[512 + tid];
    out[(size_t)node * 256 + tid] = __float2half(acc);
    float p1 = acc * asrc[tid];
    float p2 = acc * adst[tid];
#pragma unroll
    for (int o = 16; o; o >>= 1) {
        p1 += __shfl_xor_sync(0xFFFFFFFFu, p1, o);
        p2 += __shfl_xor_sync(0xFFFFFFFFu, p2, o);
    }
    int warp = tid >> 5, lane = tid & 31;
    if (!lane) { r1[warp] = p1; r2[warp] = p2; }
    __syncthreads();
    if (tid < 4) {
        g_ssrc[node * 4 + tid] = r1[tid * 2] + r1[tid * 2 + 1];
        g_sdst[node * 4 + tid] = r2[tid * 2] + r2[tid * 2 + 1];
    }
}

// =====================================================================
// fp16 tensor-core GEMM (m16n8k16, fp32 accum), double-buffered smem,
// fused attn-logit epilogue. A: fp16 [M][K]; Bt: fp16 [N][K].
// =====================================================================
#define APH 24  // halves per smem row (16 data + 8 pad) = 48B, conflict-free

__global__ __launch_bounds__(256) void mma_gemm_h(
    const __half* __restrict__ A, const __half* __restrict__ Bt,
    float* __restrict__ C, __half* __restrict__ Ch, int out_half,
    int M, int N, int K,
    const float* __restrict__ asrc, const float* __restrict__ adst,
    int C_head, int H) {
    __shared__ uint4 As4[2][128 * APH / 8];
    __shared__ uint4 Bs4[2][128 * APH / 8];

    int tid = threadIdx.x;
    int warp = tid >> 5, lane = tid & 31;
    int gid = lane >> 2, tig = lane & 3;
    int wm = warp & 3, wn = warp >> 2;
    int bm = blockIdx.x * 128, bn = blockIdx.y * 128;
    int lr = tid >> 1, lk = (tid & 1) * 8;  // load row + k8 offset

    float acc[2][8][4];
#pragma unroll
    for (int i = 0; i < 2; i++)
#pragma unroll
        for (int j = 0; j < 8; j++)
#pragma unroll
            for (int r = 0; r < 4; r++) acc[i][j][r] = 0.f;

    const uint4 z4 = make_uint4(0, 0, 0, 0);
    uint4 ra, rb;
    // prefetch tile 0
    ra = (bm + lr < M) ? *(const uint4*)&A[(size_t)(bm + lr) * K + lk] : z4;
    rb = (bn + lr < N) ? *(const uint4*)&Bt[(size_t)(bn + lr) * K + lk] : z4;
    {
        __half* As = (__half*)As4[0];
        __half* Bs = (__half*)Bs4[0];
        *(uint4*)&As[lr * APH + lk] = ra;
        *(uint4*)&Bs[lr * APH + lk] = rb;
    }
    __syncthreads();

    int cur = 0;
    for (int k0 = 0; k0 < K; k0 += 16) {
        bool has_next = (k0 + 16) < K;
        if (has_next) {
            int kn = k0 + 16;
            ra = (bm + lr < M) ? *(const uint4*)&A[(size_t)(bm + lr) * K + kn + lk] : z4;
            rb = (bn + lr < N) ? *(const uint4*)&Bt[(size_t)(bn + lr) * K + kn + lk] : z4;
        }
        const __half* As = (const __half*)As4[cur];
        const __half* Bs = (const __half*)Bs4[cur];
        unsigned af[2][4], bf[8][2];
#pragma unroll
        for (int mt = 0; mt < 2; mt++) {
            int row = wm * 32 + mt * 16 + gid;
            af[mt][0] = *(const unsigned*)&As[row * APH + 2 * tig];
            af[mt][1] = *(const unsigned*)&As[(row + 8) * APH + 2 * tig];
            af[mt][2] = *(const unsigned*)&As[row * APH + 2 * tig + 8];
            af[mt][3] = *(const unsigned*)&As[(row + 8) * APH + 2 * tig + 8];
        }
#pragma unroll
        for (int nt = 0; nt < 8; nt++) {
            int col = wn * 64 + nt * 8 + gid;
            bf[nt][0] = *(const unsigned*)&Bs[col * APH + 2 * tig];
            bf[nt][1] = *(const unsigned*)&Bs[col * APH + 2 * tig + 8];
        }
#pragma unroll
        for (int mt = 0; mt < 2; mt++)
#pragma unroll
            for (int nt = 0; nt < 8; nt++) {
                asm volatile(
                    "mma.sync.aligned.m16n8k16.row.col.f32.f16.f16.f32 "
                    "{%0,%1,%2,%3}, {%4,%5,%6,%7}, {%8,%9}, {%0,%1,%2,%3};"
                    : "+f"(acc[mt][nt][0]), "+f"(acc[mt][nt][1]),
                      "+f"(acc[mt][nt][2]), "+f"(acc[mt][nt][3])
                    : "r"(af[mt][0]), "r"(af[mt][1]), "r"(af[mt][2]), "r"(af[mt][3]),
                      "r"(bf[nt][0]), "r"(bf[nt][1]));
            }
        if (has_next) {
            int nb = cur ^ 1;
            __half* Asn = (__half*)As4[nb];
            __half* Bsn = (__half*)Bs4[nb];
            *(uint4*)&Asn[lr * APH + lk] = ra;
            *(uint4*)&Bsn[lr * APH + lk] = rb;
            __syncthreads();
            cur = nb;
        }
    }

    // ---------------- store C (fp16 or fp32) ----------------
#pragma unroll
    for (int mt = 0; mt < 2; mt++) {
#pragma unroll
        for (int nt = 0; nt < 8; nt++) {
            int col = bn + wn * 64 + nt * 8 + 2 * tig;
            if (col >= N) continue;
            int row0 = bm + wm * 32 + mt * 16 + gid;
            if (out_half) {
                if (row0 < M)
                    *(__half2*)&Ch[(size_t)row0 * N + col] =
                        __float22half2_rn(make_float2(acc[mt][nt][0], acc[mt][nt][1]));
                if (row0 + 8 < M)
                    *(__half2*)&Ch[(size_t)(row0 + 8) * N + col] =
                        __float22half2_rn(make_float2(acc[mt][nt][2], acc[mt][nt][3]));
            } else {
                if (row0 < M)
                    *(float2*)&C[(size_t)row0 * N + col] =
                        make_float2(acc[mt][nt][0], acc[mt][nt][1]);
                if (row0 + 8 < M)
                    *(float2*)&C[(size_t)(row0 + 8) * N + col] =
                        make_float2(acc[mt][nt][2], acc[mt][nt][3]);
            }
        }
    }

    // ------------- fused attention-logit epilogue (fp32 regs) -------------
    int wcb = bn + wn * 64;
    if (wcb < N) {
        int hd = wcb / C_head;
        float psrc[2][2] = {{0.f, 0.f}, {0.f, 0.f}};
        float pdst[2][2] = {{0.f, 0.f}, {0.f, 0.f}};
#pragma unroll
        for (int nt = 0; nt < 8; nt++) {
            int col = wcb + nt * 8 + 2 * tig;
            if (col >= N) continue;
            int cih = col - hd * C_head;
            float a0s = asrc[hd * C_head + cih], a1s = asrc[hd * C_head + cih + 1];
            float a0d = adst[hd * C_head + cih], a1d = adst[hd * C_head + cih + 1];
#pragma unroll
            for (int mt = 0; mt < 2; mt++) {
                psrc[mt][0] += acc[mt][nt][0] * a0s + acc[mt][nt][1] * a1s;
                pdst[mt][0] += acc[mt][nt][0] * a0d + acc[mt][nt][1] * a1d;
                psrc[mt][1] += acc[mt][nt][2] * a0s + acc[mt][nt][3] * a1s;
                pdst[mt][1] += acc[mt][nt][2] * a0d + acc[mt][nt][3] * a1d;
            }
        }
#pragma unroll
        for (int o = 1; o < 4; o <<= 1) {
#pragma unroll
            for (int mt = 0; mt < 2; mt++) {
#pragma unroll
                for (int hf = 0; hf < 2; hf++) {
                    psrc[mt][hf] += __shfl_xor_sync(0xFFFFFFFFu, psrc[mt][hf], o);
                    pdst[mt][hf] += __shfl_xor_sync(0xFFFFFFFFu, pdst[mt][hf], o);
                }
            }
        }
        if (tig == 0) {
#pragma unroll
            for (int mt = 0; mt < 2; mt++) {
#pragma unroll
                for (int hf = 0; hf < 2; hf++) {
                    int row = bm + wm * 32 + mt * 16 + gid + hf * 8;
                    if (row < M) {
                        g_ssrc[row * H + hd] = psrc[mt][hf];
                        g_sdst[row * H + hd] = pdst[mt][hf];
                    }
                }
            }
        }
    }
}

// =====================================================================
// Warp-per-node GAT propagate (H=4, C=64), fp16 in, fp16 out
// =====================================================================
__global__ __launch_bounds__(256) void gat_warp4(
    const __half* __restrict__ h, const float* __restrict__ bias,
    __half* __restrict__ out, int n, int do_relu) {
    __shared__ float sw[8][128];

    int wid = threadIdx.x >> 5, lane = threadIdx.x & 31;
    int node = blockIdx.x * 8 + wid;
    if (node >= n) return;
    int e0 = g_rowptr[node], e1 = g_rowptr[node + 1];
    float4 sd = *(const float4*)&g_sdst[node * 4];
    int hd = lane >> 3;

    float4 m4 = make_float4(NEG_INF, NEG_INF, NEG_INF, NEG_INF);
    float4 s4 = make_float4(0.f, 0.f, 0.f, 0.f);
    float4 acc0 = make_float4(0.f, 0.f, 0.f, 0.f);
    float4 acc1 = make_float4(0.f, 0.f, 0.f, 0.f);

    for (int c0 = e0; c0 < e1; c0 += 32) {
        int cs = min(32, e1 - c0);
        int src = 0;
        float4 lg = make_float4(NEG_INF, NEG_INF, NEG_INF, NEG_INF);
        if (lane < cs) {
            src = g_csr_src[c0 + lane];
            float4 ss = *(const float4*)&g_ssrc[src * 4];
            lg.x = ss.x + sd.x; lg.x = lg.x >= 0.f ? lg.x : 0.2f * lg.x;
            lg.y = ss.y + sd.y; lg.y = lg.y >= 0.f ? lg.y : 0.2f * lg.y;
            lg.z = ss.z + sd.z; lg.z = lg.z >= 0.f ? lg.z : 0.2f * lg.z;
            lg.w = ss.w + sd.w; lg.w = lg.w >= 0.f ? lg.w : 0.2f * lg.w;
        }
        float4 cm = lg;
#pragma unroll
        for (int o = 16; o; o >>= 1) {
            cm.x = fmaxf(cm.x, __shfl_xor_sync(0xFFFFFFFFu, cm.x, o));
            cm.y = fmaxf(cm.y, __shfl_xor_sync(0xFFFFFFFFu, cm.y, o));
            cm.z = fmaxf(cm.z, __shfl_xor_sync(0xFFFFFFFFu, cm.z, o));
            cm.w = fmaxf(cm.w, __shfl_xor_sync(0xFFFFFFFFu, cm.w, o));
        }
        float4 mnew = make_float4(fmaxf(m4.x, cm.x), fmaxf(m4.y, cm.y),
                                  fmaxf(m4.z, cm.z), fmaxf(m4.w, cm.w));
        float4 f = make_float4(__expf(m4.x - mnew.x), __expf(m4.y - mnew.y),
                               __expf(m4.z - mnew.z), __expf(m4.w - mnew.w));
        float fh = pick4(f, hd);
        acc0.x *= fh; acc0.y *= fh; acc0.z *= fh; acc0.w *= fh;
        acc1.x *= fh; acc1.y *= fh; acc1.z *= fh; acc1.w *= fh;
        s4.x *= f.x; s4.y *= f.y; s4.z *= f.z; s4.w *= f.w;
        m4 = mnew;
        float4 w = make_float4(0.f, 0.f, 0.f, 0.f);
        if (lane < cs) {
            w.x = __expf(lg.x - m4.x); w.y = __expf(lg.y - m4.y);
            w.z = __expf(lg.z - m4.z); w.w = __expf(lg.w - m4.w);
        }
        float4 ws = w;
#pragma unroll
        for (int o = 16; o; o >>= 1) {
            ws.x += __shfl_xor_sync(0xFFFFFFFFu, ws.x, o);
            ws.y += __shfl_xor_sync(0xFFFFFFFFu, ws.y, o);
            ws.z += __shfl_xor_sync(0xFFFFFFFFu, ws.z, o);
            ws.w += __shfl_xor_sync(0xFFFFFFFFu, ws.w, o);
        }
        s4.x += ws.x; s4.y += ws.y; s4.z += ws.z; s4.w += ws.w;
        *(float4*)&sw[wid][lane * 4] = w;
        __syncwarp();

        // ---- aggregation: fp16 rows, 4x unrolled ----
        int e = 0;
        for (; e + 4 <= cs; e += 4) {
            int se0 = __shfl_sync(0xFFFFFFFFu, src, e);
            int se1 = __shfl_sync(0xFFFFFFFFu, src, e + 1);
            int se2 = __shfl_sync(0xFFFFFFFFu, src, e + 2);
            int se3 = __shfl_sync(0xFFFFFFFFu, src, e + 3);
            float w0 = sw[wid][(e + 0) * 4 + hd];
            float w1 = sw[wid][(e + 1) * 4 + hd];
            float w2 = sw[wid][(e + 2) * 4 + hd];
            float w3 = sw[wid][(e + 3) * 4 + hd];
            uint4 u0 = ((const uint4*)(h + (size_t)se0 * 256))[lane];
            uint4 u1 = ((const uint4*)(h + (size_t)se1 * 256))[lane];
            uint4 u2 = ((const uint4*)(h + (size_t)se2 * 256))[lane];
            uint4 u3 = ((const uint4*)(h + (size_t)se3 * 256))[lane];
#define ACC_H8(u, wgt)                                                        \
            {                                                                 \
                float2 t0 = __half22float2(*(__half2*)&(u).x);                \
                float2 t1 = __half22float2(*(__half2*)&(u).y);                \
                float2 t2 = __half22float2(*(__half2*)&(u).z);                \
                float2 t3 = __half22float2(*(__half2*)&(u).w);                \
                acc0.x += (wgt) * t0.x; acc0.y += (wgt) * t0.y;               \
                acc0.z += (wgt) * t1.x; acc0.w += (wgt) * t1.y;               \
                acc1.x += (wgt) * t2.x; acc1.y += (wgt) * t2.y;               \
                acc1.z += (wgt) * t3.x; acc1.w += (wgt) * t3.y;               \
            }
            ACC_H8(u0, w0) ACC_H8(u1, w1) ACC_H8(u2, w2) ACC_H8(u3, w3)
        }
        for (; e < cs; e++) {
            int se = __shfl_sync(0xFFFFFFFFu, src, e);
            float we = sw[wid][e * 4 + hd];
            uint4 u = ((const uint4*)(h + (size_t)se * 256))[lane];
            ACC_H8(u, we)
        }
#undef ACC_H8
        __syncwarp();
    }
    float inv = 1.f / pick4(s4, hd);
    float4 b0 = *(const float4*)&bias[lane * 8];
    float4 b1 = *(const float4*)&bias[lane * 8 + 4];
    float4 o0, o1;
    o0.x = acc0.x * inv + b0.x; o0.y = acc0.y * inv + b0.y;
    o0.z = acc0.z * inv + b0.z; o0.w = acc0.w * inv + b0.w;
    o1.x = acc1.x * inv + b1.x; o1.y = acc1.y * inv + b1.y;
    o1.z = acc1.z * inv + b1.z; o1.w = acc1.w * inv + b1.w;
    if (do_relu) {
        o0.x = fmaxf(o0.x, 0.f); o0.y = fmaxf(o0.y, 0.f);
        o0.z = fmaxf(o0.z, 0.f); o0.w = fmaxf(o0.w, 0.f);
        o1.x = fmaxf(o1.x, 0.f); o1.y = fmaxf(o1.y, 0.f);
        o1.z = fmaxf(o1.z, 0.f); o1.w = fmaxf(o1.w, 0.f);
    }
    // pack 8 floats -> 8 halves -> one 16B store
    uint4 uo;
    *(__half2*)&uo.x = __float22half2_rn(make_float2(o0.x, o0.y));
    *(__half2*)&uo.y = __float22half2_rn(make_float2(o0.z, o0.w));
    *(__half2*)&uo.z = __float22half2_rn(make_float2(o1.x, o1.y));
    *(__half2*)&uo.w = __float22half2_rn(make_float2(o1.z, o1.w));
    ((uint4*)(out + (size_t)node * 256))[lane] = uo;
}

// =====================================================================
// Fused GAT propagate (H=1, C=32): warp per dst node, fp32 h (final layer)
// =====================================================================
__global__ void gat_fused1(const float* __restrict__ h, const float* __restrict__ bias,
                           float* __restrict__ out, int n) {
    int w = (blockIdx.x * blockDim.x + threadIdx.x) >> 5;
    int lane = threadIdx.x & 31;
    if (w >= n) return;
    int node = w;
    int e0 = g_rowptr[node], e1 = g_rowptr[node + 1];
    float sdst = g_sdst[node];
    float m = NEG_INF, s = 0.f, acc = 0.f;
    for (int c0 = e0; c0 < e1; c0 += 32) {
        int cs = min(32, e1 - c0);
        int src = (lane < cs) ? g_csr_src[c0 + lane] : 0;
        float v = NEG_INF;
        if (lane < cs) {
            v = g_ssrc[src] + sdst;
            v = v >= 0.f ? v : 0.2f * v;
        }
        float cm = v;
#pragma unroll
        for (int o = 16; o; o >>= 1) cm = fmaxf(cm, __shfl_xor_sync(0xFFFFFFFFu, cm, o));
        float mnew = fmaxf(m, cm);
        float f = __expf(m - mnew);
        acc *= f; s *= f; m = mnew;
        float wv = (lane < cs) ? __expf(v - m) : 0.f;
        float ps = wv;
#pragma unroll
        for (int o = 16; o; o >>= 1) ps += __shfl_xor_sync(0xFFFFFFFFu, ps, o);
        s += ps;
        int e = 0;
        for (; e + 4 <= cs; e += 4) {
            float w0 = __shfl_sync(0xFFFFFFFFu, wv, e);
            float w1 = __shfl_sync(0xFFFFFFFFu, wv, e + 1);
            float w2 = __shfl_sync(0xFFFFFFFFu, wv, e + 2);
            float w3 = __shfl_sync(0xFFFFFFFFu, wv, e + 3);
            int s0 = __shfl_sync(0xFFFFFFFFu, src, e);
            int s1 = __shfl_sync(0xFFFFFFFFu, src, e + 1);
            int s2 = __shfl_sync(0xFFFFFFFFu, src, e + 2);
            int s3 = __shfl_sync(0xFFFFFFFFu, src, e + 3);
            float v0 = h[(size_t)s0 * 32 + lane];
            float v1 = h[(size_t)s1 * 32 + lane];
            float v2 = h[(size_t)s2 * 32 + lane];
            float v3 = h[(size_t)s3 * 32 + lane];
            acc += w0 * v0 + w1 * v1 + w2 * v2 + w3 * v3;
        }
        for (; e < cs; e++) {
            float we = __shfl_sync(0xFFFFFFFFu, wv, e);
            int se = __shfl_sync(0xFFFFFFFFu, src, e);
            acc += we * h[(size_t)se * 32 + lane];
        }
    }
    out[(size_t)node * 32 + lane] = acc / s + bias[lane];
}

extern "C" void kernel_launch(void* const* d_in, const int* in_sizes, int n_in,
                              void* d_out, int out_size) {
    const float* x      = (const float*)d_in[0];
    const int*   ei     = (const int*)d_in[1];
    const float* W1     = (const float*)d_in[2];
    const float* a_src1 = (const float*)d_in[3];
    const float* a_dst1 = (const float*)d_in[4];
    const float* b1     = (const float*)d_in[5];
    const float* W2     = (const float*)d_in[6];
    const float* a_src2 = (const float*)d_in[7];
    const float* a_dst2 = (const float*)d_in[8];
    const float* b2     = (const float*)d_in[9];
    const float* W3     = (const float*)d_in[10];
    const float* a_src3 = (const float*)d_in[11];
    const float* a_dst3 = (const float*)d_in[12];
    const float* b3     = (const float*)d_in[13];
    float* out = (float*)d_out;

    int n = in_sizes[0] / 3;
    int E = in_sizes[1] / 2;
    int Etot = E + n;

    float* gB;
    __half *gAh, *gBh, *gW2h, *gW3h;
    cudaGetSymbolAddress((void**)&gB, g_B);
    cudaGetSymbolAddress((void**)&gAh, g_Ah4);
    cudaGetSymbolAddress((void**)&gBh, g_Bh4);
    cudaGetSymbolAddress((void**)&gW2h, g_W2h4);
    cudaGetSymbolAddress((void**)&gW3h, g_W3h4);

    int nb = (n + 255) / 256;
    int nw8 = (n + 7) / 8;
    dim3 g2((n + 127) / 128, 2);
    dim3 g3((n + 127) / 128, 1);
    dim3 cvtb(32, 8);

    // ---------------- weight convert (fp32 -> fp16 transposed) ----------------
    w_cvt<<<dim3(8, 8), cvtb>>>(W2, gW2h, 256, 256);
    w_cvt<<<dim3(1, 8), cvtb>>>(W3, gW3h, 256, 32);

    // ---------------- CSR build ----------------
    csr_count<<<(E + 255) / 256, 256>>>(ei, E);
    scan_part<<<nb, 256>>>(n);
    scan_top<<<1, 32>>>(nb);
    scan_fin<<<nb, 256>>>(n);
    csr_fill<<<(Etot + 255) / 256, 256>>>(ei, E, Etot);

    // ---------------- Layer 1 ----------------
    gemm_l1_attn<<<n, 256>>>(x, W1, a_src1, a_dst1, gBh, n);
    gat_warp4<<<nw8, 256>>>(gBh, b1, gAh, n, 1);

    // ---------------- Layer 2 ----------------
    mma_gemm_h<<<g2, 256>>>(gAh, gW2h, nullptr, gBh, 1, n, 256, 256, a_src2, a_dst2, 64, 4);
    gat_warp4<<<nw8, 256>>>(gBh, b2, gAh, n, 1);

    // ---------------- Layer 3 ----------------
    mma_gemm_h<<<g3, 256>>>(gAh, gW3h, gB, nullptr, 0, n, 32, 256, a_src3, a_dst3, 32, 1);
    gat_fused1<<<(n * 32 + 255) / 256, 256>>>(gB, b3, out, n);
}

// round 13
// speedup vs baseline: 1.3420x; 1.0262x over previous
#include <cuda_runtime.h>
#include <cuda_fp16.h>

#define NMAX 50000
#define EMAXE 400000
#define ETOTMAX (EMAXE + NMAX)
#define NEG_INF __int_as_float(0xff800000)

// Scratch (static device globals — allocation-free)
__device__ uint4  g_Ah4[NMAX * 32];     // fp16 feature buffer (GEMM input / gat output)
__device__ uint4  g_Bh4[NMAX * 32];     // fp16 h (gat input, layers 1-2)
__device__ float  g_B[NMAX * 32];       // fp32 h (layer 3)
__device__ uint4  g_W2h4[256 * 32];     // W2^T fp16 [N=256][K=256]
__device__ uint4  g_W3h4[32 * 32];      // W3^T fp16 [N=32][K=256]
__device__ float  g_ssrc[NMAX * 4];     // per-node src attention logits [N,H]
__device__ float  g_sdst[NMAX * 4];     // per-node dst attention logits [N,H]
__device__ int    g_csr_src[ETOTMAX];   // CSR: src ids grouped by dst
__device__ int    g_rowptr[NMAX + 1];   // CSR row pointers
__device__ int    g_wptr[NMAX];         // counts / write cursors (0 at start of every run)

__device__ __forceinline__ float pick4(float4 v, int i) {
    float ab = (i & 1) ? v.y : v.x;
    float cd = (i & 1) ? v.w : v.z;
    return (i & 2) ? cd : ab;
}

__device__ __forceinline__ void ldsm_x4(unsigned& r0, unsigned& r1, unsigned& r2,
                                        unsigned& r3, unsigned saddr) {
    asm volatile("ldmatrix.sync.aligned.m8n8.x4.shared.b16 {%0,%1,%2,%3}, [%4];"
                 : "=r"(r0), "=r"(r1), "=r"(r2), "=r"(r3) : "r"(saddr));
}

// ============== weight convert (both W2 and W3 in one launch) ==============
// W[K][N] fp32 -> Wt[N][K] fp16.  Blocks 0-63: W2 (8x8 tiles); 64-71: W3 (1x8).
__global__ void w_cvt2(const float* __restrict__ W2, const float* __restrict__ W3,
                       __half* __restrict__ W2t, __half* __restrict__ W3t) {
    __shared__ float t[32][33];
    int b = blockIdx.x;
    const float* W; __half* Wt; int K, N, k0, n0;
    if (b < 64) { W = W2; Wt = W2t; K = 256; N = 256; n0 = (b & 7) * 32; k0 = (b >> 3) * 32; }
    else        { W = W3; Wt = W3t; K = 256; N = 32;  n0 = 0;            k0 = (b - 64) * 32; }
    int tx = threadIdx.x, ty = threadIdx.y;  // 32 x 8
    for (int i = ty; i < 32; i += 8) {
        int k = k0 + i, n = n0 + tx;
        t[i][tx] = (k < K && n < N) ? W[(size_t)k * N + n] : 0.f;
    }
    __syncthreads();
    for (int i = ty; i < 32; i += 8) {
        int n = n0 + i, k = k0 + tx;
        if (n < N && k < K) Wt[(size_t)n * K + k] = __float2half(t[tx][i]);
    }
}

// ============================ CSR construction ============================
__global__ void csr_count(const int* __restrict__ ei, int E) {
    int e = blockIdx.x * blockDim.x + threadIdx.x;
    if (e < E) atomicAdd(&g_wptr[ei[E + e]], 1);
}

// single-block exclusive scan of (wptr[i]+1) -> rowptr; resets wptr. 1024 thr.
__global__ void scan_all(int n) {
    __shared__ int wsum[32];
    __shared__ int s_carry;
    int tid = threadIdx.x, lane = tid & 31, warp = tid >> 5;
    if (tid == 0) s_carry = 0;
    __syncthreads();
    int nq = (n + 3) >> 2;
    for (int base = 0; base < nq; base += 1024) {
        int i0 = (base + tid) * 4;
        int4 v4 = make_int4(0, 0, 0, 0);
        if (i0 + 3 < n) {
            v4 = *(const int4*)&g_wptr[i0];
            v4.x += 1; v4.y += 1; v4.z += 1; v4.w += 1;
        } else if (i0 < n) {
            int* vp = &v4.x;
            for (int j = 0; j < 4; j++) if (i0 + j < n) vp[j] = g_wptr[i0 + j] + 1;
        }
        int tsum = v4.x + v4.y + v4.z + v4.w;
        int x = tsum;
#pragma unroll
        for (int o = 1; o < 32; o <<= 1) {
            int t = __shfl_up_sync(0xFFFFFFFFu, x, o);
            if (lane >= o) x += t;
        }
        if (lane == 31) wsum[warp] = x;
        __syncthreads();
        if (warp == 0) {
            int s = wsum[lane];
#pragma unroll
            for (int o = 1; o < 32; o <<= 1) {
                int t = __shfl_up_sync(0xFFFFFFFFu, s, o);
                if (lane >= o) s += t;
            }
            wsum[lane] = s;
        }
        __syncthreads();
        int carry = s_carry;
        int total = wsum[31];
        int excl = carry + (warp ? wsum[warp - 1] : 0) + x - tsum;
        if (i0 + 3 < n) {
            int4 r;
            r.x = excl;
            r.y = excl + v4.x;
            r.z = r.y + v4.y;
            r.w = r.z + v4.z;
            *(int4*)&g_rowptr[i0] = r;
            *(int4*)&g_wptr[i0] = make_int4(0, 0, 0, 0);
        } else if (i0 < n) {
            int run = excl;
            int* vp = &v4.x;
            for (int j = 0; j < 4 && i0 + j < n; j++) {
                g_rowptr[i0 + j] = run; run += vp[j]; g_wptr[i0 + j] = 0;
            }
        }
        __syncthreads();
        if (tid == 0) s_carry = carry + total;
    }
    __syncthreads();
    if (tid == 0) g_rowptr[n] = s_carry;
}

__global__ void csr_fill(const int* __restrict__ ei, int E, int Etot) {
    int e = blockIdx.x * blockDim.x + threadIdx.x;
    if (e >= Etot) return;
    int s, d;
    if (e < E) { s = ei[e]; d = ei[E + e]; } else { s = d = e - E; }
    int pos = atomicAdd(&g_wptr[d], 1);
    g_csr_src[g_rowptr[d] + pos] = s;
}

// ============== layer 1 GEMM + fused attention logits (fp16 h out) ==============
__global__ void gemm_l1_attn(const float* __restrict__ x, const float* __restrict__ W,
                             const float* __restrict__ asrc, const float* __restrict__ adst,
                             __half* __restrict__ out, int n) {
    __shared__ float xs[3];
    __shared__ float r1[8], r2[8];
    int node = blockIdx.x;
    if (node >= n) return;
    int tid = threadIdx.x;
    if (tid < 3) xs[tid] = x[node * 3 + tid];
    if (tid == 32) g_wptr[node] = 0;  // cursor reset for next replay
    __syncthreads();
    float acc = xs[0] * W[tid] + xs[1] * W[256 + tid] + xs[2] * W[512 + tid];
    out[(size_t)node * 256 + tid] = __float2half(acc);
    float p1 = acc * asrc[tid];
    float p2 = acc * adst[tid];
#pragma unroll
    for (int o = 16; o; o >>= 1) {
        p1 += __shfl_xor_sync(0xFFFFFFFFu, p1, o);
        p2 += __shfl_xor_sync(0xFFFFFFFFu, p2, o);
    }
    int warp = tid >> 5, lane = tid & 31;
    if (!lane) { r1[warp] = p1; r2[warp] = p2; }
    __syncthreads();
    if (tid < 4) {
        g_ssrc[node * 4 + tid] = r1[tid * 2] + r1[tid * 2 + 1];
        g_sdst[node * 4 + tid] = r2[tid * 2] + r2[tid * 2 + 1];
    }
}

// =====================================================================
// fp16 tensor-core GEMM (m16n8k16, fp32 accum), ldmatrix fragment loads,
// double-buffered smem, fused attn-logit epilogue.
// A: fp16 [M][K]; Bt: fp16 [N][K].
// =====================================================================
#define APH 24  // halves per smem row (16 data + 8 pad) = 48B; conflict-free LDSM

__global__ __launch_bounds__(256) void mma_gemm_h(
    const __half* __restrict__ A, const __half* __restrict__ Bt,
    float* __restrict__ C, __half* __restrict__ Ch, int out_half,
    int M, int N, int K,
    const float* __restrict__ asrc, const float* __restrict__ adst,
    int C_head, int H) {
    __shared__ uint4 As4[2][128 * APH / 8];
    __shared__ uint4 Bs4[2][128 * APH / 8];

    int tid = threadIdx.x;
    int warp = tid >> 5, lane = tid & 31;
    int gid = lane >> 2, tig = lane & 3;
    int wm = warp & 3, wn = warp >> 2;
    int bm = blockIdx.x * 128, bn = blockIdx.y * 128;
    int lr = tid >> 1, lk = (tid & 1) * 8;  // load row + k8 offset

    // ldmatrix per-lane byte offsets (within one buffer)
    unsigned sAs = (unsigned)__cvta_generic_to_shared(As4);
    unsigned sBs = (unsigned)__cvta_generic_to_shared(Bs4);
    unsigned aoff0 = ((unsigned)((wm * 32 + (lane & 15)) * APH + ((lane >> 4) << 3))) * 2u;
    unsigned aoff1 = aoff0 + 16u * APH * 2u;
    unsigned boffp[4];
#pragma unroll
    for (int p = 0; p < 4; p++) {
        int q = lane >> 3;
        int col = wn * 64 + p * 16 + ((q >> 1) << 3) + (lane & 7);
        int koff = (q & 1) << 3;
        boffp[p] = ((unsigned)(col * APH + koff)) * 2u;
    }

    float acc[2][8][4];
#pragma unroll
    for (int i = 0; i < 2; i++)
#pragma unroll
        for (int j = 0; j < 8; j++)
#pragma unroll
            for (int r = 0; r < 4; r++) acc[i][j][r] = 0.f;

    const uint4 z4 = make_uint4(0, 0, 0, 0);
    uint4 ra, rb;
    ra = (bm + lr < M) ? *(const uint4*)&A[(size_t)(bm + lr) * K + lk] : z4;
    rb = (bn + lr < N) ? *(const uint4*)&Bt[(size_t)(bn + lr) * K + lk] : z4;
    {
        __half* As = (__half*)As4[0];
        __half* Bs = (__half*)Bs4[0];
        *(uint4*)&As[lr * APH + lk] = ra;
        *(uint4*)&Bs[lr * APH + lk] = rb;
    }
    __syncthreads();

    int cur = 0;
    for (int k0 = 0; k0 < K; k0 += 16) {
        bool has_next = (k0 + 16) < K;
        if (has_next) {
            int kn = k0 + 16;
            ra = (bm + lr < M) ? *(const uint4*)&A[(size_t)(bm + lr) * K + kn + lk] : z4;
            rb = (bn + lr < N) ? *(const uint4*)&Bt[(size_t)(bn + lr) * K + kn + lk] : z4;
        }
        unsigned ab = sAs + (unsigned)cur * 6144u;
        unsigned bb = sBs + (unsigned)cur * 6144u;
        unsigned af[2][4], bf[8][2];
        ldsm_x4(af[0][0], af[0][1], af[0][2], af[0][3], ab + aoff0);
        ldsm_x4(af[1][0], af[1][1], af[1][2], af[1][3], ab + aoff1);
        ldsm_x4(bf[0][0], bf[0][1], bf[1][0], bf[1][1], bb + boffp[0]);
        ldsm_x4(bf[2][0], bf[2][1], bf[3][0], bf[3][1], bb + boffp[1]);
        ldsm_x4(bf[4][0], bf[4][1], bf[5][0], bf[5][1], bb + boffp[2]);
        ldsm_x4(bf[6][0], bf[6][1], bf[7][0], bf[7][1], bb + boffp[3]);
#pragma unroll
        for (int mt = 0; mt < 2; mt++)
#pragma unroll
            for (int nt = 0; nt < 8; nt++) {
                asm volatile(
                    "mma.sync.aligned.m16n8k16.row.col.f32.f16.f16.f32 "
                    "{%0,%1,%2,%3}, {%4,%5,%6,%7}, {%8,%9}, {%0,%1,%2,%3};"
                    : "+f"(acc[mt][nt][0]), "+f"(acc[mt][nt][1]),
                      "+f"(acc[mt][nt][2]), "+f"(acc[mt][nt][3])
                    : "r"(af[mt][0]), "r"(af[mt][1]), "r"(af[mt][2]), "r"(af[mt][3]),
                      "r"(bf[nt][0]), "r"(bf[nt][1]));
            }
        if (has_next) {
            int nb = cur ^ 1;
            __half* Asn = (__half*)As4[nb];
            __half* Bsn = (__half*)Bs4[nb];
            *(uint4*)&Asn[lr * APH + lk] = ra;
            *(uint4*)&Bsn[lr * APH + lk] = rb;
            __syncthreads();
            cur = nb;
        }
    }

    // ---------------- store C (fp16 or fp32) ----------------
#pragma unroll
    for (int mt = 0; mt < 2; mt++) {
#pragma unroll
        for (int nt = 0; nt < 8; nt++) {
            int col = bn + wn * 64 + nt * 8 + 2 * tig;
            if (col >= N) continue;
            int row0 = bm + wm * 32 + mt * 16 + gid;
            if (out_half) {
                if (row0 < M)
                    *(__half2*)&Ch[(size_t)row0 * N + col] =
                        __float22half2_rn(make_float2(acc[mt][nt][0], acc[mt][nt][1]));
                if (row0 + 8 < M)
                    *(__half2*)&Ch[(size_t)(row0 + 8) * N + col] =
                        __float22half2_rn(make_float2(acc[mt][nt][2], acc[mt][nt][3]));
            } else {
                if (row0 < M)
                    *(float2*)&C[(size_t)row0 * N + col] =
                        make_float2(acc[mt][nt][0], acc[mt][nt][1]);
                if (row0 + 8 < M)
                    *(float2*)&C[(size_t)(row0 + 8) * N + col] =
                        make_float2(acc[mt][nt][2], acc[mt][nt][3]);
            }
        }
    }

    // ------------- fused attention-logit epilogue (fp32 regs) -------------
    int wcb = bn + wn * 64;
    if (wcb < N) {
        int hd = wcb / C_head;
        float psrc[2][2] = {{0.f, 0.f}, {0.f, 0.f}};
        float pdst[2][2] = {{0.f, 0.f}, {0.f, 0.f}};
#pragma unroll
        for (int nt = 0; nt < 8; nt++) {
            int col = wcb + nt * 8 + 2 * tig;
            if (col >= N) continue;
            int cih = col - hd * C_head;
            float a0s = asrc[hd * C_head + cih], a1s = asrc[hd * C_head + cih + 1];
            float a0d = adst[hd * C_head + cih], a1d = adst[hd * C_head + cih + 1];
#pragma unroll
            for (int mt = 0; mt < 2; mt++) {
                psrc[mt][0] += acc[mt][nt][0] * a0s + acc[mt][nt][1] * a1s;
                pdst[mt][0] += acc[mt][nt][0] * a0d + acc[mt][nt][1] * a1d;
                psrc[mt][1] += acc[mt][nt][2] * a0s + acc[mt][nt][3] * a1s;
                pdst[mt][1] += acc[mt][nt][2] * a0d + acc[mt][nt][3] * a1d;
            }
        }
#pragma unroll
        for (int o = 1; o < 4; o <<= 1) {
#pragma unroll
            for (int mt = 0; mt < 2; mt++) {
#pragma unroll
                for (int hf = 0; hf < 2; hf++) {
                    psrc[mt][hf] += __shfl_xor_sync(0xFFFFFFFFu, psrc[mt][hf], o);
                    pdst[mt][hf] += __shfl_xor_sync(0xFFFFFFFFu, pdst[mt][hf], o);
                }
            }
        }
        if (tig == 0) {
#pragma unroll
            for (int mt = 0; mt < 2; mt++) {
#pragma unroll
                for (int hf = 0; hf < 2; hf++) {
                    int row = bm + wm * 32 + mt * 16 + gid + hf * 8;
                    if (row < M) {
                        g_ssrc[row * H + hd] = psrc[mt][hf];
                        g_sdst[row * H + hd] = pdst[mt][hf];
                    }
                }
            }
        }
    }
}

// =====================================================================
// Warp-per-node GAT propagate (H=4, C=64), fp16 in/out,
// first-chunk fast path (no online-softmax merge).
// =====================================================================
template <bool FIRST>
__device__ __forceinline__ void gat4_chunk(
    const __half* __restrict__ h, int c0, int cs, float4 sd, int hd, int lane,
    float* swp, float4& m4, float4& s4, float4& acc0, float4& acc1) {
    int src = 0;
    float4 lg = make_float4(NEG_INF, NEG_INF, NEG_INF, NEG_INF);
    if (lane < cs) {
        src = g_csr_src[c0 + lane];
        float4 ss = *(const float4*)&g_ssrc[src * 4];
        lg.x = ss.x + sd.x; lg.x = lg.x >= 0.f ? lg.x : 0.2f * lg.x;
        lg.y = ss.y + sd.y; lg.y = lg.y >= 0.f ? lg.y : 0.2f * lg.y;
        lg.z = ss.z + sd.z; lg.z = lg.z >= 0.f ? lg.z : 0.2f * lg.z;
        lg.w = ss.w + sd.w; lg.w = lg.w >= 0.f ? lg.w : 0.2f * lg.w;
    }
    float4 cm = lg;
#pragma unroll
    for (int o = 16; o; o >>= 1) {
        cm.x = fmaxf(cm.x, __shfl_xor_sync(0xFFFFFFFFu, cm.x, o));
        cm.y = fmaxf(cm.y, __shfl_xor_sync(0xFFFFFFFFu, cm.y, o));
        cm.z = fmaxf(cm.z, __shfl_xor_sync(0xFFFFFFFFu, cm.z, o));
        cm.w = fmaxf(cm.w, __shfl_xor_sync(0xFFFFFFFFu, cm.w, o));
    }
    if (FIRST) {
        m4 = cm;
    } else {
        float4 mnew = make_float4(fmaxf(m4.x, cm.x), fmaxf(m4.y, cm.y),
                                  fmaxf(m4.z, cm.z), fmaxf(m4.w, cm.w));
        float4 f = make_float4(__expf(m4.x - mnew.x), __expf(m4.y - mnew.y),
                               __expf(m4.z - mnew.z), __expf(m4.w - mnew.w));
        float fh = pick4(f, hd);
        acc0.x *= fh; acc0.y *= fh; acc0.z *= fh; acc0.w *= fh;
        acc1.x *= fh; acc1.y *= fh; acc1.z *= fh; acc1.w *= fh;
        s4.x *= f.x; s4.y *= f.y; s4.z *= f.z; s4.w *= f.w;
        m4 = mnew;
    }
    float4 w = make_float4(0.f, 0.f, 0.f, 0.f);
    if (lane < cs) {
        w.x = __expf(lg.x - m4.x); w.y = __expf(lg.y - m4.y);
        w.z = __expf(lg.z - m4.z); w.w = __expf(lg.w - m4.w);
    }
    float4 ws = w;
#pragma unroll
    for (int o = 16; o; o >>= 1) {
        ws.x += __shfl_xor_sync(0xFFFFFFFFu, ws.x, o);
        ws.y += __shfl_xor_sync(0xFFFFFFFFu, ws.y, o);
        ws.z += __shfl_xor_sync(0xFFFFFFFFu, ws.z, o);
        ws.w += __shfl_xor_sync(0xFFFFFFFFu, ws.w, o);
    }
    if (FIRST) { s4 = ws; }
    else { s4.x += ws.x; s4.y += ws.y; s4.z += ws.z; s4.w += ws.w; }
    *(float4*)&swp[lane * 4] = w;
    __syncwarp();

    int e = 0;
    for (; e + 4 <= cs; e += 4) {
        int se0 = __shfl_sync(0xFFFFFFFFu, src, e);
        int se1 = __shfl_sync(0xFFFFFFFFu, src, e + 1);
        int se2 = __shfl_sync(0xFFFFFFFFu, src, e + 2);
        int se3 = __shfl_sync(0xFFFFFFFFu, src, e + 3);
        float w0 = swp[(e + 0) * 4 + hd];
        float w1 = swp[(e + 1) * 4 + hd];
        float w2 = swp[(e + 2) * 4 + hd];
        float w3 = swp[(e + 3) * 4 + hd];
        uint4 u0 = ((const uint4*)(h + (size_t)se0 * 256))[lane];
        uint4 u1 = ((const uint4*)(h + (size_t)se1 * 256))[lane];
        uint4 u2 = ((const uint4*)(h + (size_t)se2 * 256))[lane];
        uint4 u3 = ((const uint4*)(h + (size_t)se3 * 256))[lane];
#define ACC_H8(u, wgt)                                                    \
        {                                                                 \
            float2 t0 = __half22float2(*(__half2*)&(u).x);                \
            float2 t1 = __half22float2(*(__half2*)&(u).y);                \
            float2 t2 = __half22float2(*(__half2*)&(u).z);                \
            float2 t3 = __half22float2(*(__half2*)&(u).w);                \
            acc0.x += (wgt) * t0.x; acc0.y += (wgt) * t0.y;               \
            acc0.z += (wgt) * t1.x; acc0.w += (wgt) * t1.y;               \
            acc1.x += (wgt) * t2.x; acc1.y += (wgt) * t2.y;               \
            acc1.z += (wgt) * t3.x; acc1.w += (wgt) * t3.y;               \
        }
        ACC_H8(u0, w0) ACC_H8(u1, w1) ACC_H8(u2, w2) ACC_H8(u3, w3)
    }
    for (; e < cs; e++) {
        int se = __shfl_sync(0xFFFFFFFFu, src, e);
        float we = swp[e * 4 + hd];
        uint4 u = ((const uint4*)(h + (size_t)se * 256))[lane];
        ACC_H8(u, we)
    }
#undef ACC_H8
    __syncwarp();
}

__global__ __launch_bounds__(256) void gat_warp4(
    const __half* __restrict__ h, const float* __restrict__ bias,
    __half* __restrict__ out, int n, int do_relu) {
    __shared__ float sw[8][128];

    int wid = threadIdx.x >> 5, lane = threadIdx.x & 31;
    int node = blockIdx.x * 8 + wid;
    if (node >= n) return;
    int e0 = g_rowptr[node], e1 = g_rowptr[node + 1];
    float4 sd = *(const float4*)&g_sdst[node * 4];
    int hd = lane >> 3;
    float* swp = sw[wid];

    float4 m4 = make_float4(NEG_INF, NEG_INF, NEG_INF, NEG_INF);
    float4 s4 = make_float4(0.f, 0.f, 0.f, 0.f);
    float4 acc0 = make_float4(0.f, 0.f, 0.f, 0.f);
    float4 acc1 = make_float4(0.f, 0.f, 0.f, 0.f);

    // first chunk (deg >= 1 always — self-loop)
    gat4_chunk<true>(h, e0, min(32, e1 - e0), sd, hd, lane, swp, m4, s4, acc0, acc1);
    for (int c0 = e0 + 32; c0 < e1; c0 += 32)
        gat4_chunk<false>(h, c0, min(32, e1 - c0), sd, hd, lane, swp, m4, s4, acc0, acc1);

    float inv = 1.f / pick4(s4, hd);
    float4 b0 = *(const float4*)&bias[lane * 8];
    float4 b1 = *(const float4*)&bias[lane * 8 + 4];
    float4 o0, o1;
    o0.x = acc0.x * inv + b0.x; o0.y = acc0.y * inv + b0.y;
    o0.z = acc0.z * inv + b0.z; o0.w = acc0.w * inv + b0.w;
    o1.x = acc1.x * inv + b1.x; o1.y = acc1.y * inv + b1.y;
    o1.z = acc1.z * inv + b1.z; o1.w = acc1.w * inv + b1.w;
    if (do_relu) {
        o0.x = fmaxf(o0.x, 0.f); o0.y = fmaxf(o0.y, 0.f);
        o0.z = fmaxf(o0.z, 0.f); o0.w = fmaxf(o0.w, 0.f);
        o1.x = fmaxf(o1.x, 0.f); o1.y = fmaxf(o1.y, 0.f);
        o1.z = fmaxf(o1.z, 0.f); o1.w = fmaxf(o1.w, 0.f);
    }
    uint4 uo;
    *(__half2*)&uo.x = __float22half2_rn(make_float2(o0.x, o0.y));
    *(__half2*)&uo.y = __float22half2_rn(make_float2(o0.z, o0.w));
    *(__half2*)&uo.z = __float22half2_rn(make_float2(o1.x, o1.y));
    *(__half2*)&uo.w = __float22half2_rn(make_float2(o1.z, o1.w));
    ((uint4*)(out + (size_t)node * 256))[lane] = uo;
}

// =====================================================================
// Fused GAT propagate (H=1, C=32): warp per dst node, fp32 h (final layer)
// =====================================================================
__global__ void gat_fused1(const float* __restrict__ h, const float* __restrict__ bias,
                           float* __restrict__ out, int n) {
    int w = (blockIdx.x * blockDim.x + threadIdx.x) >> 5;
    int lane = threadIdx.x & 31;
    if (w >= n) return;
    int node = w;
    int e0 = g_rowptr[node], e1 = g_rowptr[node + 1];
    float sdst = g_sdst[node];
    float m = NEG_INF, s = 0.f, acc = 0.f;
    for (int c0 = e0; c0 < e1; c0 += 32) {
        int cs = min(32, e1 - c0);
        int src = (lane < cs) ? g_csr_src[c0 + lane] : 0;
        float v = NEG_INF;
        if (lane < cs) {
            v = g_ssrc[src] + sdst;
            v = v >= 0.f ? v : 0.2f * v;
        }
        float cm = v;
#pragma unroll
        for (int o = 16; o; o >>= 1) cm = fmaxf(cm, __shfl_xor_sync(0xFFFFFFFFu, cm, o));
        float mnew = fmaxf(m, cm);
        float f = __expf(m - mnew);
        acc *= f; s *= f; m = mnew;
        float wv = (lane < cs) ? __expf(v - m) : 0.f;
        float ps = wv;
#pragma unroll
        for (int o = 16; o; o >>= 1) ps += __shfl_xor_sync(0xFFFFFFFFu, ps, o);
        s += ps;
        int e = 0;
        for (; e + 4 <= cs; e += 4) {
            float w0 = __shfl_sync(0xFFFFFFFFu, wv, e);
            float w1 = __shfl_sync(0xFFFFFFFFu, wv, e + 1);
            float w2 = __shfl_sync(0xFFFFFFFFu, wv, e + 2);
            float w3 = __shfl_sync(0xFFFFFFFFu, wv, e + 3);
            int s0 = __shfl_sync(0xFFFFFFFFu, src, e);
            int s1 = __shfl_sync(0xFFFFFFFFu, src, e + 1);
            int s2 = __shfl_sync(0xFFFFFFFFu, src, e + 2);
            int s3 = __shfl_sync(0xFFFFFFFFu, src, e + 3);
            float v0 = h[(size_t)s0 * 32 + lane];
            float v1 = h[(size_t)s1 * 32 + lane];
            float v2 = h[(size_t)s2 * 32 + lane];
            float v3 = h[(size_t)s3 * 32 + lane];
            acc += w0 * v0 + w1 * v1 + w2 * v2 + w3 * v3;
        }
        for (; e < cs; e++) {
            float we = __shfl_sync(0xFFFFFFFFu, wv, e);
            int se = __shfl_sync(0xFFFFFFFFu, src, e);
            acc += we * h[(size_t)se * 32 + lane];
        }
    }
    out[(size_t)node * 32 + lane] = acc / s + bias[lane];
}

extern "C" void kernel_launch(void* const* d_in, const int* in_sizes, int n_in,
                              void* d_out, int out_size) {
    const float* x      = (const float*)d_in[0];
    const int*   ei     = (const int*)d_in[1];
    const float* W1     = (const float*)d_in[2];
    const float* a_src1 = (const float*)d_in[3];
    const float* a_dst1 = (const float*)d_in[4];
    const float* b1     = (const float*)d_in[5];
    const float* W2     = (const float*)d_in[6];
    const float* a_src2 = (const float*)d_in[7];
    const float* a_dst2 = (const float*)d_in[8];
    const float* b2     = (const float*)d_in[9];
    const float* W3     = (const float*)d_in[10];
    const float* a_src3 = (const float*)d_in[11];
    const float* a_dst3 = (const float*)d_in[12];
    const float* b3     = (const float*)d_in[13];
    float* out = (float*)d_out;

    int n = in_sizes[0] / 3;
    int E = in_sizes[1] / 2;
    int Etot = E + n;

    float* gB;
    __half *gAh, *gBh, *gW2h, *gW3h;
    cudaGetSymbolAddress((void**)&gB, g_B);
    cudaGetSymbolAddress((void**)&gAh, g_Ah4);
    cudaGetSymbolAddress((void**)&gBh, g_Bh4);
    cudaGetSymbolAddress((void**)&gW2h, g_W2h4);
    cudaGetSymbolAddress((void**)&gW3h, g_W3h4);

    int nw8 = (n + 7) / 8;
    dim3 g2((n + 127) / 128, 2);
    dim3 g3((n + 127) / 128, 1);

    // ---------------- weight convert + CSR build ----------------
    w_cvt2<<<72, dim3(32, 8)>>>(W2, W3, gW2h, gW3h);
    csr_count<<<(E + 255) / 256, 256>>>(ei, E);
    scan_all<<<1, 1024>>>(n);
    csr_fill<<<(Etot + 255) / 256, 256>>>(ei, E, Etot);

    // ---------------- Layer 1 ----------------
    gemm_l1_attn<<<n, 256>>>(x, W1, a_src1, a_dst1, gBh, n);
    gat_warp4<<<nw8, 256>>>(gBh, b1, gAh, n, 1);

    // ---------------- Layer 2 ----------------
    mma_gemm_h<<<g2, 256>>>(gAh, gW2h, nullptr, gBh, 1, n, 256, 256, a_src2, a_dst2, 64, 4);
    gat_warp4<<<nw8, 256>>>(gBh, b2, gAh, n, 1);

    // ---------------- Layer 3 ----------------
    mma_gemm_h<<<g3, 256>>>(gAh, gW3h, gB, nullptr, 0, n, 32, 256, a_src3, a_dst3, 32, 1);
    gat_fused1<<<(n * 32 + 255) / 256, 256>>>(gB, b3, out, n);
}

// round 14
// speedup vs baseline: 1.3859x; 1.0327x over previous
#include <cuda_runtime.h>
#include <cuda_fp16.h>

#define NMAX 50000
#define EMAXE 400000
#define ETOTMAX (EMAXE + NMAX)
#define NEG_INF __int_as_float(0xff800000)

// Scratch (static device globals — allocation-free)
__device__ uint4  g_Ah4[NMAX * 32];     // fp16 feature buffer (GEMM input / gat output)
__device__ uint4  g_Bh4[NMAX * 32];     // fp16 h (gat input, layers 1-2)
__device__ float  g_B[NMAX * 32];       // fp32 h (layer 3)
__device__ uint4  g_W2h4[256 * 32];     // W2^T fp16 [N=256][K=256]
__device__ uint4  g_W3h4[32 * 32];      // W3^T fp16 [N=32][K=256]
__device__ float  g_ssrc[NMAX * 4];     // per-node src attention logits [N,H]
__device__ float  g_sdst[NMAX * 4];     // per-node dst attention logits [N,H]
__device__ int    g_csr_src[ETOTMAX];   // CSR: src ids grouped by dst
__device__ int    g_rowptr[NMAX + 1];   // CSR row pointers
__device__ int    g_wptr[NMAX];         // counts / write cursors (0 at start of every run)

__device__ __forceinline__ float pick4(float4 v, int i) {
    float ab = (i & 1) ? v.y : v.x;
    float cd = (i & 1) ? v.w : v.z;
    return (i & 2) ? cd : ab;
}

__device__ __forceinline__ void ldsm_x4(unsigned& r0, unsigned& r1, unsigned& r2,
                                        unsigned& r3, unsigned saddr) {
    asm volatile("ldmatrix.sync.aligned.m8n8.x4.shared.b16 {%0,%1,%2,%3}, [%4];"
                 : "=r"(r0), "=r"(r1), "=r"(r2), "=r"(r3) : "r"(saddr));
}

// ============== weight convert (both W2 and W3 in one launch) ==============
__global__ void w_cvt2(const float* __restrict__ W2, const float* __restrict__ W3,
                       __half* __restrict__ W2t, __half* __restrict__ W3t) {
    __shared__ float t[32][33];
    int b = blockIdx.x;
    const float* W; __half* Wt; int K, N, k0, n0;
    if (b < 64) { W = W2; Wt = W2t; K = 256; N = 256; n0 = (b & 7) * 32; k0 = (b >> 3) * 32; }
    else        { W = W3; Wt = W3t; K = 256; N = 32;  n0 = 0;            k0 = (b - 64) * 32; }
    int tx = threadIdx.x, ty = threadIdx.y;  // 32 x 8
    for (int i = ty; i < 32; i += 8) {
        int k = k0 + i, n = n0 + tx;
        t[i][tx] = (k < K && n < N) ? W[(size_t)k * N + n] : 0.f;
    }
    __syncthreads();
    for (int i = ty; i < 32; i += 8) {
        int n = n0 + i, k = k0 + tx;
        if (n < N && k < K) Wt[(size_t)n * K + k] = __float2half(t[tx][i]);
    }
}

// ============================ CSR construction ============================
// 2 edges per thread (E is even -> int2 alignment holds)
__global__ void csr_count(const int* __restrict__ ei, int E) {
    int e = (blockIdx.x * blockDim.x + threadIdx.x) * 2;
    if (e + 1 < E) {
        int2 d2 = *(const int2*)&ei[E + e];
        atomicAdd(&g_wptr[d2.x], 1);
        atomicAdd(&g_wptr[d2.y], 1);
    } else if (e < E) {
        atomicAdd(&g_wptr[ei[E + e]], 1);
    }
}

// single-block exclusive scan of (wptr[i]+1) -> rowptr; resets wptr. 1024 thr.
__global__ void scan_all(int n) {
    __shared__ int wsum[32];
    __shared__ int s_carry;
    int tid = threadIdx.x, lane = tid & 31, warp = tid >> 5;
    if (tid == 0) s_carry = 0;
    __syncthreads();
    int nq = (n + 3) >> 2;
    for (int base = 0; base < nq; base += 1024) {
        int i0 = (base + tid) * 4;
        int4 v4 = make_int4(0, 0, 0, 0);
        if (i0 + 3 < n) {
            v4 = *(const int4*)&g_wptr[i0];
            v4.x += 1; v4.y += 1; v4.z += 1; v4.w += 1;
        } else if (i0 < n) {
            int* vp = &v4.x;
            for (int j = 0; j < 4; j++) if (i0 + j < n) vp[j] = g_wptr[i0 + j] + 1;
        }
        int tsum = v4.x + v4.y + v4.z + v4.w;
        int x = tsum;
#pragma unroll
        for (int o = 1; o < 32; o <<= 1) {
            int t = __shfl_up_sync(0xFFFFFFFFu, x, o);
            if (lane >= o) x += t;
        }
        if (lane == 31) wsum[warp] = x;
        __syncthreads();
        if (warp == 0) {
            int s = wsum[lane];
#pragma unroll
            for (int o = 1; o < 32; o <<= 1) {
                int t = __shfl_up_sync(0xFFFFFFFFu, s, o);
                if (lane >= o) s += t;
            }
            wsum[lane] = s;
        }
        __syncthreads();
        int carry = s_carry;
        int total = wsum[31];
        int excl = carry + (warp ? wsum[warp - 1] : 0) + x - tsum;
        if (i0 + 3 < n) {
            int4 r;
            r.x = excl;
            r.y = excl + v4.x;
            r.z = r.y + v4.y;
            r.w = r.z + v4.z;
            *(int4*)&g_rowptr[i0] = r;
            *(int4*)&g_wptr[i0] = make_int4(0, 0, 0, 0);
        } else if (i0 < n) {
            int run = excl;
            int* vp = &v4.x;
            for (int j = 0; j < 4 && i0 + j < n; j++) {
                g_rowptr[i0 + j] = run; run += vp[j]; g_wptr[i0 + j] = 0;
            }
        }
        __syncthreads();
        if (tid == 0) s_carry = carry + total;
    }
    __syncthreads();
    if (tid == 0) g_rowptr[n] = s_carry;
}

// 2 edges per thread
__global__ void csr_fill(const int* __restrict__ ei, int E, int Etot) {
    int e = (blockIdx.x * blockDim.x + threadIdx.x) * 2;
    if (e >= Etot) return;
    if (e + 1 < E) {
        int2 s2 = *(const int2*)&ei[e];
        int2 d2 = *(const int2*)&ei[E + e];
        int p0 = atomicAdd(&g_wptr[d2.x], 1);
        g_csr_src[g_rowptr[d2.x] + p0] = s2.x;
        int p1 = atomicAdd(&g_wptr[d2.y], 1);
        g_csr_src[g_rowptr[d2.y] + p1] = s2.y;
    } else {
#pragma unroll
        for (int j = 0; j < 2; j++) {
            int ee = e + j;
            if (ee >= Etot) break;
            int s, d;
            if (ee < E) { s = ei[ee]; d = ei[E + ee]; } else { s = d = ee - E; }
            int pos = atomicAdd(&g_wptr[d], 1);
            g_csr_src[g_rowptr[d] + pos] = s;
        }
    }
}

// ============== layer 1 GEMM + fused attention logits (fp16 h out) ==============
__global__ void gemm_l1_attn(const float* __restrict__ x, const float* __restrict__ W,
                             const float* __restrict__ asrc, const float* __restrict__ adst,
                             __half* __restrict__ out, int n) {
    __shared__ float xs[3];
    __shared__ float r1[8], r2[8];
    int node = blockIdx.x;
    if (node >= n) return;
    int tid = threadIdx.x;
    if (tid < 3) xs[tid] = x[node * 3 + tid];
    if (tid == 32) g_wptr[node] = 0;  // cursor reset for next replay
    __syncthreads();
    float acc = xs[0] * W[tid] + xs[1] * W[256 + tid] + xs[2] * W[512 + tid];
    out[(size_t)node * 256 + tid] = __float2half(acc);
    float p1 = acc * asrc[tid];
    float p2 = acc * adst[tid];
#pragma unroll
    for (int o = 16; o; o >>= 1) {
        p1 += __shfl_xor_sync(0xFFFFFFFFu, p1, o);
        p2 += __shfl_xor_sync(0xFFFFFFFFu, p2, o);
    }
    int warp = tid >> 5, lane = tid & 31;
    if (!lane) { r1[warp] = p1; r2[warp] = p2; }
    __syncthreads();
    if (tid < 4) {
        g_ssrc[node * 4 + tid] = r1[tid * 2] + r1[tid * 2 + 1];
        g_sdst[node * 4 + tid] = r2[tid * 2] + r2[tid * 2 + 1];
    }
}

// =====================================================================
// fp16 tensor-core GEMM (m16n8k16, fp32 accum), ldmatrix fragment loads,
// double-buffered smem, fused attn-logit epilogue. (layer 2: N=256)
// =====================================================================
#define APH 24  // halves per smem row (16 data + 8 pad) = 48B; conflict-free LDSM

__global__ __launch_bounds__(256) void mma_gemm_h(
    const __half* __restrict__ A, const __half* __restrict__ Bt,
    __half* __restrict__ Ch,
    int M, int N, int K,
    const float* __restrict__ asrc, const float* __restrict__ adst,
    int C_head, int H) {
    __shared__ uint4 As4[2][128 * APH / 8];
    __shared__ uint4 Bs4[2][128 * APH / 8];

    int tid = threadIdx.x;
    int warp = tid >> 5, lane = tid & 31;
    int gid = lane >> 2, tig = lane & 3;
    int wm = warp & 3, wn = warp >> 2;
    int bm = blockIdx.x * 128, bn = blockIdx.y * 128;
    int lr = tid >> 1, lk = (tid & 1) * 8;

    unsigned sAs = (unsigned)__cvta_generic_to_shared(As4);
    unsigned sBs = (unsigned)__cvta_generic_to_shared(Bs4);
    unsigned aoff0 = ((unsigned)((wm * 32 + (lane & 15)) * APH + ((lane >> 4) << 3))) * 2u;
    unsigned aoff1 = aoff0 + 16u * APH * 2u;
    unsigned boffp[4];
#pragma unroll
    for (int p = 0; p < 4; p++) {
        int q = lane >> 3;
        int col = wn * 64 + p * 16 + ((q >> 1) << 3) + (lane & 7);
        int koff = (q & 1) << 3;
        boffp[p] = ((unsigned)(col * APH + koff)) * 2u;
    }

    float acc[2][8][4];
#pragma unroll
    for (int i = 0; i < 2; i++)
#pragma unroll
        for (int j = 0; j < 8; j++)
#pragma unroll
            for (int r = 0; r < 4; r++) acc[i][j][r] = 0.f;

    const uint4 z4 = make_uint4(0, 0, 0, 0);
    uint4 ra, rb;
    ra = (bm + lr < M) ? *(const uint4*)&A[(size_t)(bm + lr) * K + lk] : z4;
    rb = (bn + lr < N) ? *(const uint4*)&Bt[(size_t)(bn + lr) * K + lk] : z4;
    {
        __half* As = (__half*)As4[0];
        __half* Bs = (__half*)Bs4[0];
        *(uint4*)&As[lr * APH + lk] = ra;
        *(uint4*)&Bs[lr * APH + lk] = rb;
    }
    __syncthreads();

    int cur = 0;
    for (int k0 = 0; k0 < K; k0 += 16) {
        bool has_next = (k0 + 16) < K;
        if (has_next) {
            int kn = k0 + 16;
            ra = (bm + lr < M) ? *(const uint4*)&A[(size_t)(bm + lr) * K + kn + lk] : z4;
            rb = (bn + lr < N) ? *(const uint4*)&Bt[(size_t)(bn + lr) * K + kn + lk] : z4;
        }
        unsigned ab = sAs + (unsigned)cur * 6144u;
        unsigned bb = sBs + (unsigned)cur * 6144u;
        unsigned af[2][4], bf[8][2];
        ldsm_x4(af[0][0], af[0][1], af[0][2], af[0][3], ab + aoff0);
        ldsm_x4(af[1][0], af[1][1], af[1][2], af[1][3], ab + aoff1);
        ldsm_x4(bf[0][0], bf[0][1], bf[1][0], bf[1][1], bb + boffp[0]);
        ldsm_x4(bf[2][0], bf[2][1], bf[3][0], bf[3][1], bb + boffp[1]);
        ldsm_x4(bf[4][0], bf[4][1], bf[5][0], bf[5][1], bb + boffp[2]);
        ldsm_x4(bf[6][0], bf[6][1], bf[7][0], bf[7][1], bb + boffp[3]);
#pragma unroll
        for (int mt = 0; mt < 2; mt++)
#pragma unroll
            for (int nt = 0; nt < 8; nt++) {
                asm volatile(
                    "mma.sync.aligned.m16n8k16.row.col.f32.f16.f16.f32 "
                    "{%0,%1,%2,%3}, {%4,%5,%6,%7}, {%8,%9}, {%0,%1,%2,%3};"
                    : "+f"(acc[mt][nt][0]), "+f"(acc[mt][nt][1]),
                      "+f"(acc[mt][nt][2]), "+f"(acc[mt][nt][3])
                    : "r"(af[mt][0]), "r"(af[mt][1]), "r"(af[mt][2]), "r"(af[mt][3]),
                      "r"(bf[nt][0]), "r"(bf[nt][1]));
            }
        if (has_next) {
            int nb = cur ^ 1;
            __half* Asn = (__half*)As4[nb];
            __half* Bsn = (__half*)Bs4[nb];
            *(uint4*)&Asn[lr * APH + lk] = ra;
            *(uint4*)&Bsn[lr * APH + lk] = rb;
            __syncthreads();
            cur = nb;
        }
    }

#pragma unroll
    for (int mt = 0; mt < 2; mt++) {
#pragma unroll
        for (int nt = 0; nt < 8; nt++) {
            int col = bn + wn * 64 + nt * 8 + 2 * tig;
            if (col >= N) continue;
            int row0 = bm + wm * 32 + mt * 16 + gid;
            if (row0 < M)
                *(__half2*)&Ch[(size_t)row0 * N + col] =
                    __float22half2_rn(make_float2(acc[mt][nt][0], acc[mt][nt][1]));
            if (row0 + 8 < M)
                *(__half2*)&Ch[(size_t)(row0 + 8) * N + col] =
                    __float22half2_rn(make_float2(acc[mt][nt][2], acc[mt][nt][3]));
        }
    }

    int wcb = bn + wn * 64;
    if (wcb < N) {
        int hd = wcb / C_head;
        float psrc[2][2] = {{0.f, 0.f}, {0.f, 0.f}};
        float pdst[2][2] = {{0.f, 0.f}, {0.f, 0.f}};
#pragma unroll
        for (int nt = 0; nt < 8; nt++) {
            int col = wcb + nt * 8 + 2 * tig;
            if (col >= N) continue;
            int cih = col - hd * C_head;
            float a0s = asrc[hd * C_head + cih], a1s = asrc[hd * C_head + cih + 1];
            float a0d = adst[hd * C_head + cih], a1d = adst[hd * C_head + cih + 1];
#pragma unroll
            for (int mt = 0; mt < 2; mt++) {
                psrc[mt][0] += acc[mt][nt][0] * a0s + acc[mt][nt][1] * a1s;
                pdst[mt][0] += acc[mt][nt][0] * a0d + acc[mt][nt][1] * a1d;
                psrc[mt][1] += acc[mt][nt][2] * a0s + acc[mt][nt][3] * a1s;
                pdst[mt][1] += acc[mt][nt][2] * a0d + acc[mt][nt][3] * a1d;
            }
        }
#pragma unroll
        for (int o = 1; o < 4; o <<= 1) {
#pragma unroll
            for (int mt = 0; mt < 2; mt++) {
#pragma unroll
                for (int hf = 0; hf < 2; hf++) {
                    psrc[mt][hf] += __shfl_xor_sync(0xFFFFFFFFu, psrc[mt][hf], o);
                    pdst[mt][hf] += __shfl_xor_sync(0xFFFFFFFFu, pdst[mt][hf], o);
                }
            }
        }
        if (tig == 0) {
#pragma unroll
            for (int mt = 0; mt < 2; mt++) {
#pragma unroll
                for (int hf = 0; hf < 2; hf++) {
                    int row = bm + wm * 32 + mt * 16 + gid + hf * 8;
                    if (row < M) {
                        g_ssrc[row * H + hd] = psrc[mt][hf];
                        g_sdst[row * H + hd] = pdst[mt][hf];
                    }
                }
            }
        }
    }
}

// =====================================================================
// Layer-3 specialized GEMM: N=32, block tile 128x32, 8 warps all on M.
// Warp tile 16x32 (1 A-frag set, 4 B-tiles). fp32 out. H=1, C_head=32.
// =====================================================================
__global__ __launch_bounds__(256) void mma_gemm_h32(
    const __half* __restrict__ A, const __half* __restrict__ Bt,
    float* __restrict__ C, int M, int K,
    const float* __restrict__ asrc, const float* __restrict__ adst) {
    __shared__ uint4 As4[2][128 * APH / 8];
    __shared__ uint4 Bs4[2][32 * APH / 8];

    int tid = threadIdx.x;
    int warp = tid >> 5, lane = tid & 31;
    int gid = lane >> 2, tig = lane & 3;
    int wm = warp;                       // 8 m-tiles of 16 rows
    int bm = blockIdx.x * 128;
    int lr = tid >> 1, lk = (tid & 1) * 8;

    unsigned sAs = (unsigned)__cvta_generic_to_shared(As4);
    unsigned sBs = (unsigned)__cvta_generic_to_shared(Bs4);
    unsigned aoff = ((unsigned)((wm * 16 + (lane & 15)) * APH + ((lane >> 4) << 3))) * 2u;
    unsigned boffp[2];
#pragma unroll
    for (int p = 0; p < 2; p++) {
        int q = lane >> 3;
        int col = p * 16 + ((q >> 1) << 3) + (lane & 7);
        int koff = (q & 1) << 3;
        boffp[p] = ((unsigned)(col * APH + koff)) * 2u;
    }

    float acc[4][4];
#pragma unroll
    for (int j = 0; j < 4; j++)
#pragma unroll
        for (int r = 0; r < 4; r++) acc[j][r] = 0.f;

    const uint4 z4 = make_uint4(0, 0, 0, 0);
    uint4 ra, rb = z4;
    ra = (bm + lr < M) ? *(const uint4*)&A[(size_t)(bm + lr) * K + lk] : z4;
    if (tid < 64) rb = *(const uint4*)&Bt[(size_t)lr * K + lk];
    {
        __half* As = (__half*)As4[0];
        *(uint4*)&As[lr * APH + lk] = ra;
        if (tid < 64) { __half* Bs = (__half*)Bs4[0]; *(uint4*)&Bs[lr * APH + lk] = rb; }
    }
    __syncthreads();

    int cur = 0;
    for (int k0 = 0; k0 < K; k0 += 16) {
        bool has_next = (k0 + 16) < K;
        if (has_next) {
            int kn = k0 + 16;
            ra = (bm + lr < M) ? *(const uint4*)&A[(size_t)(bm + lr) * K + kn + lk] : z4;
            if (tid < 64) rb = *(const uint4*)&Bt[(size_t)lr * K + kn + lk];
        }
        unsigned ab = sAs + (unsigned)cur * 6144u;
        unsigned bb = sBs + (unsigned)cur * 1536u;
        unsigned af[4], bf[4][2];
        ldsm_x4(af[0], af[1], af[2], af[3], ab + aoff);
        ldsm_x4(bf[0][0], bf[0][1], bf[1][0], bf[1][1], bb + boffp[0]);
        ldsm_x4(bf[2][0], bf[2][1], bf[3][0], bf[3][1], bb + boffp[1]);
#pragma unroll
        for (int nt = 0; nt < 4; nt++) {
            asm volatile(
                "mma.sync.aligned.m16n8k16.row.col.f32.f16.f16.f32 "
                "{%0,%1,%2,%3}, {%4,%5,%6,%7}, {%8,%9}, {%0,%1,%2,%3};"
                : "+f"(acc[nt][0]), "+f"(acc[nt][1]),
                  "+f"(acc[nt][2]), "+f"(acc[nt][3])
                : "r"(af[0]), "r"(af[1]), "r"(af[2]), "r"(af[3]),
                  "r"(bf[nt][0]), "r"(bf[nt][1]));
        }
        if (has_next) {
            int nb = cur ^ 1;
            __half* Asn = (__half*)As4[nb];
            *(uint4*)&Asn[lr * APH + lk] = ra;
            if (tid < 64) { __half* Bsn = (__half*)Bs4[nb]; *(uint4*)&Bsn[lr * APH + lk] = rb; }
            __syncthreads();
            cur = nb;
        }
    }

    // store C fp32 [M][32]
#pragma unroll
    for (int nt = 0; nt < 4; nt++) {
        int col = nt * 8 + 2 * tig;
        int row0 = bm + wm * 16 + gid;
        if (row0 < M)
            *(float2*)&C[(size_t)row0 * 32 + col] = make_float2(acc[nt][0], acc[nt][1]);
        if (row0 + 8 < M)
            *(float2*)&C[(size_t)(row0 + 8) * 32 + col] = make_float2(acc[nt][2], acc[nt][3]);
    }

    // fused attn logits (H=1)
    {
        float psrc[2] = {0.f, 0.f}, pdst[2] = {0.f, 0.f};
#pragma unroll
        for (int nt = 0; nt < 4; nt++) {
            int col = nt * 8 + 2 * tig;
            float a0s = asrc[col], a1s = asrc[col + 1];
            float a0d = adst[col], a1d = adst[col + 1];
            psrc[0] += acc[nt][0] * a0s + acc[nt][1] * a1s;
            pdst[0] += acc[nt][0] * a0d + acc[nt][1] * a1d;
            psrc[1] += acc[nt][2] * a0s + acc[nt][3] * a1s;
            pdst[1] += acc[nt][2] * a0d + acc[nt][3] * a1d;
        }
#pragma unroll
        for (int o = 1; o < 4; o <<= 1) {
#pragma unroll
            for (int hf = 0; hf < 2; hf++) {
                psrc[hf] += __shfl_xor_sync(0xFFFFFFFFu, psrc[hf], o);
                pdst[hf] += __shfl_xor_sync(0xFFFFFFFFu, pdst[hf], o);
            }
        }
        if (tig == 0) {
#pragma unroll
            for (int hf = 0; hf < 2; hf++) {
                int row = bm + wm * 16 + gid + hf * 8;
                if (row < M) { g_ssrc[row] = psrc[hf]; g_sdst[row] = pdst[hf]; }
            }
        }
    }
}

// =====================================================================
// Warp-per-node GAT propagate (H=4, C=64), fp16 in/out
// =====================================================================
template <bool FIRST>
__device__ __forceinline__ void gat4_chunk(
    const __half* __restrict__ h, int c0, int cs, float4 sd, int hd, int lane,
    float* swp, float4& m4, float4& s4, float4& acc0, float4& acc1) {
    int src = 0;
    float4 lg = make_float4(NEG_INF, NEG_INF, NEG_INF, NEG_INF);
    if (lane < cs) {
        src = g_csr_src[c0 + lane];
        float4 ss = *(const float4*)&g_ssrc[src * 4];
        lg.x = ss.x + sd.x; lg.x = lg.x >= 0.f ? lg.x : 0.2f * lg.x;
        lg.y = ss.y + sd.y; lg.y = lg.y >= 0.f ? lg.y : 0.2f * lg.y;
        lg.z = ss.z + sd.z; lg.z = lg.z >= 0.f ? lg.z : 0.2f * lg.z;
        lg.w = ss.w + sd.w; lg.w = lg.w >= 0.f ? lg.w : 0.2f * lg.w;
    }
    float4 cm = lg;
#pragma unroll
    for (int o = 16; o; o >>= 1) {
        cm.x = fmaxf(cm.x, __shfl_xor_sync(0xFFFFFFFFu, cm.x, o));
        cm.y = fmaxf(cm.y, __shfl_xor_sync(0xFFFFFFFFu, cm.y, o));
        cm.z = fmaxf(cm.z, __shfl_xor_sync(0xFFFFFFFFu, cm.z, o));
        cm.w = fmaxf(cm.w, __shfl_xor_sync(0xFFFFFFFFu, cm.w, o));
    }
    if (FIRST) {
        m4 = cm;
    } else {
        float4 mnew = make_float4(fmaxf(m4.x, cm.x), fmaxf(m4.y, cm.y),
                                  fmaxf(m4.z, cm.z), fmaxf(m4.w, cm.w));
        float4 f = make_float4(__expf(m4.x - mnew.x), __expf(m4.y - mnew.y),
                               __expf(m4.z - mnew.z), __expf(m4.w - mnew.w));
        float fh = pick4(f, hd);
        acc0.x *= fh; acc0.y *= fh; acc0.z *= fh; acc0.w *= fh;
        acc1.x *= fh; acc1.y *= fh; acc1.z *= fh; acc1.w *= fh;
        s4.x *= f.x; s4.y *= f.y; s4.z *= f.z; s4.w *= f.w;
        m4 = mnew;
    }
    float4 w = make_float4(0.f, 0.f, 0.f, 0.f);
    if (lane < cs) {
        w.x = __expf(lg.x - m4.x); w.y = __expf(lg.y - m4.y);
        w.z = __expf(lg.z - m4.z); w.w = __expf(lg.w - m4.w);
    }
    float4 ws = w;
#pragma unroll
    for (int o = 16; o; o >>= 1) {
        ws.x += __shfl_xor_sync(0xFFFFFFFFu, ws.x, o);
        ws.y += __shfl_xor_sync(0xFFFFFFFFu, ws.y, o);
        ws.z += __shfl_xor_sync(0xFFFFFFFFu, ws.z, o);
        ws.w += __shfl_xor_sync(0xFFFFFFFFu, ws.w, o);
    }
    if (FIRST) { s4 = ws; }
    else { s4.x += ws.x; s4.y += ws.y; s4.z += ws.z; s4.w += ws.w; }
    *(float4*)&swp[lane * 4] = w;
    __syncwarp();

    int e = 0;
    for (; e + 4 <= cs; e += 4) {
        int se0 = __shfl_sync(0xFFFFFFFFu, src, e);
        int se1 = __shfl_sync(0xFFFFFFFFu, src, e + 1);
        int se2 = __shfl_sync(0xFFFFFFFFu, src, e + 2);
        int se3 = __shfl_sync(0xFFFFFFFFu, src, e + 3);
        float w0 = swp[(e + 0) * 4 + hd];
        float w1 = swp[(e + 1) * 4 + hd];
        float w2 = swp[(e + 2) * 4 + hd];
        float w3 = swp[(e + 3) * 4 + hd];
        uint4 u0 = ((const uint4*)(h + (size_t)se0 * 256))[lane];
        uint4 u1 = ((const uint4*)(h + (size_t)se1 * 256))[lane];
        uint4 u2 = ((const uint4*)(h + (size_t)se2 * 256))[lane];
        uint4 u3 = ((const uint4*)(h + (size_t)se3 * 256))[lane];
#define ACC_H8(u, wgt)                                                    \
        {                                                                 \
            float2 t0 = __half22float2(*(__half2*)&(u).x);                \
            float2 t1 = __half22float2(*(__half2*)&(u).y);                \
            float2 t2 = __half22float2(*(__half2*)&(u).z);                \
            float2 t3 = __half22float2(*(__half2*)&(u).w);                \
            acc0.x += (wgt) * t0.x; acc0.y += (wgt) * t0.y;               \
            acc0.z += (wgt) * t1.x; acc0.w += (wgt) * t1.y;               \
            acc1.x += (wgt) * t2.x; acc1.y += (wgt) * t2.y;               \
            acc1.z += (wgt) * t3.x; acc1.w += (wgt) * t3.y;               \
        }
        ACC_H8(u0, w0) ACC_H8(u1, w1) ACC_H8(u2, w2) ACC_H8(u3, w3)
    }
    for (; e < cs; e++) {
        int se = __shfl_sync(0xFFFFFFFFu, src, e);
        float we = swp[e * 4 + hd];
        uint4 u = ((const uint4*)(h + (size_t)se * 256))[lane];
        ACC_H8(u, we)
    }
#undef ACC_H8
    __syncwarp();
}

__global__ __launch_bounds__(256) void gat_warp4(
    const __half* __restrict__ h, const float* __restrict__ bias,
    __half* __restrict__ out, int n, int do_relu) {
    __shared__ float sw[8][128];

    int wid = threadIdx.x >> 5, lane = threadIdx.x & 31;
    int node = blockIdx.x * 8 + wid;
    if (node >= n) return;
    int e0 = g_rowptr[node], e1 = g_rowptr[node + 1];
    float4 sd = *(const float4*)&g_sdst[node * 4];
    int hd = lane >> 3;
    float* swp = sw[wid];

    float4 m4 = make_float4(NEG_INF, NEG_INF, NEG_INF, NEG_INF);
    float4 s4 = make_float4(0.f, 0.f, 0.f, 0.f);
    float4 acc0 = make_float4(0.f, 0.f, 0.f, 0.f);
    float4 acc1 = make_float4(0.f, 0.f, 0.f, 0.f);

    gat4_chunk<true>(h, e0, min(32, e1 - e0), sd, hd, lane, swp, m4, s4, acc0, acc1);
    for (int c0 = e0 + 32; c0 < e1; c0 += 32)
        gat4_chunk<false>(h, c0, min(32, e1 - c0), sd, hd, lane, swp, m4, s4, acc0, acc1);

    float inv = 1.f / pick4(s4, hd);
    float4 b0 = *(const float4*)&bias[lane * 8];
    float4 b1 = *(const float4*)&bias[lane * 8 + 4];
    float4 o0, o1;
    o0.x = acc0.x * inv + b0.x; o0.y = acc0.y * inv + b0.y;
    o0.z = acc0.z * inv + b0.z; o0.w = acc0.w * inv + b0.w;
    o1.x = acc1.x * inv + b1.x; o1.y = acc1.y * inv + b1.y;
    o1.z = acc1.z * inv + b1.z; o1.w = acc1.w * inv + b1.w;
    if (do_relu) {
        o0.x = fmaxf(o0.x, 0.f); o0.y = fmaxf(o0.y, 0.f);
        o0.z = fmaxf(o0.z, 0.f); o0.w = fmaxf(o0.w, 0.f);
        o1.x = fmaxf(o1.x, 0.f); o1.y = fmaxf(o1.y, 0.f);
        o1.z = fmaxf(o1.z, 0.f); o1.w = fmaxf(o1.w, 0.f);
    }
    uint4 uo;
    *(__half2*)&uo.x = __float22half2_rn(make_float2(o0.x, o0.y));
    *(__half2*)&uo.y = __float22half2_rn(make_float2(o0.z, o0.w));
    *(__half2*)&uo.z = __float22half2_rn(make_float2(o1.x, o1.y));
    *(__half2*)&uo.w = __float22half2_rn(make_float2(o1.z, o1.w));
    ((uint4*)(out + (size_t)node * 256))[lane] = uo;
}

// =====================================================================
// Fused GAT propagate (H=1, C=32): warp per dst node, fp32 h (final layer)
// =====================================================================
__global__ void gat_fused1(const float* __restrict__ h, const float* __restrict__ bias,
                           float* __restrict__ out, int n) {
    int w = (blockIdx.x * blockDim.x + threadIdx.x) >> 5;
    int lane = threadIdx.x & 31;
    if (w >= n) return;
    int node = w;
    int e0 = g_rowptr[node], e1 = g_rowptr[node + 1];
    float sdst = g_sdst[node];
    float m = NEG_INF, s = 0.f, acc = 0.f;
    for (int c0 = e0; c0 < e1; c0 += 32) {
        int cs = min(32, e1 - c0);
        int src = (lane < cs) ? g_csr_src[c0 + lane] : 0;
        float v = NEG_INF;
        if (lane < cs) {
            v = g_ssrc[src] + sdst;
            v = v >= 0.f ? v : 0.2f * v;
        }
        float cm = v;
#pragma unroll
        for (int o = 16; o; o >>= 1) cm = fmaxf(cm, __shfl_xor_sync(0xFFFFFFFFu, cm, o));
        float mnew = fmaxf(m, cm);
        float f = __expf(m - mnew);
        acc *= f; s *= f; m = mnew;
        float wv = (lane < cs) ? __expf(v - m) : 0.f;
        float ps = wv;
#pragma unroll
        for (int o = 16; o; o >>= 1) ps += __shfl_xor_sync(0xFFFFFFFFu, ps, o);
        s += ps;
        int e = 0;
        for (; e + 4 <= cs; e += 4) {
            float w0 = __shfl_sync(0xFFFFFFFFu, wv, e);
            float w1 = __shfl_sync(0xFFFFFFFFu, wv, e + 1);
            float w2 = __shfl_sync(0xFFFFFFFFu, wv, e + 2);
            float w3 = __shfl_sync(0xFFFFFFFFu, wv, e + 3);
            int s0 = __shfl_sync(0xFFFFFFFFu, src, e);
            int s1 = __shfl_sync(0xFFFFFFFFu, src, e + 1);
            int s2 = __shfl_sync(0xFFFFFFFFu, src, e + 2);
            int s3 = __shfl_sync(0xFFFFFFFFu, src, e + 3);
            float v0 = h[(size_t)s0 * 32 + lane];
            float v1 = h[(size_t)s1 * 32 + lane];
            float v2 = h[(size_t)s2 * 32 + lane];
            float v3 = h[(size_t)s3 * 32 + lane];
            acc += w0 * v0 + w1 * v1 + w2 * v2 + w3 * v3;
        }
        for (; e < cs; e++) {
            float we = __shfl_sync(0xFFFFFFFFu, wv, e);
            int se = __shfl_sync(0xFFFFFFFFu, src, e);
            acc += we * h[(size_t)se * 32 + lane];
        }
    }
    out[(size_t)node * 32 + lane] = acc / s + bias[lane];
}

extern "C" void kernel_launch(void* const* d_in, const int* in_sizes, int n_in,
                              void* d_out, int out_size) {
    const float* x      = (const float*)d_in[0];
    const int*   ei     = (const int*)d_in[1];
    const float* W1     = (const float*)d_in[2];
    const float* a_src1 = (const float*)d_in[3];
    const float* a_dst1 = (const float*)d_in[4];
    const float* b1     = (const float*)d_in[5];
    const float* W2     = (const float*)d_in[6];
    const float* a_src2 = (const float*)d_in[7];
    const float* a_dst2 = (const float*)d_in[8];
    const float* b2     = (const float*)d_in[9];
    const float* W3     = (const float*)d_in[10];
    const float* a_src3 = (const float*)d_in[11];
    const float* a_dst3 = (const float*)d_in[12];
    const float* b3     = (const float*)d_in[13];
    float* out = (float*)d_out;

    int n = in_sizes[0] / 3;
    int E = in_sizes[1] / 2;
    int Etot = E + n;

    float* gB;
    __half *gAh, *gBh, *gW2h, *gW3h;
    cudaGetSymbolAddress((void**)&gB, g_B);
    cudaGetSymbolAddress((void**)&gAh, g_Ah4);
    cudaGetSymbolAddress((void**)&gBh, g_Bh4);
    cudaGetSymbolAddress((void**)&gW2h, g_W2h4);
    cudaGetSymbolAddress((void**)&gW3h, g_W3h4);

    int nw8 = (n + 7) / 8;
    dim3 g2((n + 127) / 128, 2);
    int g3 = (n + 127) / 128;

    // ---------------- weight convert + CSR build ----------------
    w_cvt2<<<72, dim3(32, 8)>>>(W2, W3, gW2h, gW3h);
    csr_count<<<(E / 2 + 255) / 256, 256>>>(ei, E);
    scan_all<<<1, 1024>>>(n);
    csr_fill<<<(Etot / 2 + 256) / 256, 256>>>(ei, E, Etot);

    // ---------------- Layer 1 ----------------
    gemm_l1_attn<<<n, 256>>>(x, W1, a_src1, a_dst1, gBh, n);
    gat_warp4<<<nw8, 256>>>(gBh, b1, gAh, n, 1);

    // ---------------- Layer 2 ----------------
    mma_gemm_h<<<g2, 256>>>(gAh, gW2h, gBh, n, 256, 256, a_src2, a_dst2, 64, 4);
    gat_warp4<<<nw8, 256>>>(gBh, b2, gAh, n, 1);

    // ---------------- Layer 3 (specialized N=32) ----------------
    mma_gemm_h32<<<g3, 256>>>(gAh, gW3h, gB, n, 256, a_src3, a_dst3);
    gat_fused1<<<(n * 32 + 255) / 256, 256>>>(gB, b3, out, n);
}

// round 17
// speedup vs baseline: 1.4259x; 1.0289x over previous
#include <cuda_runtime.h>
#include <cuda_fp16.h>

#define NMAX 50000
#define EMAXE 400000
#define ETOTMAX (EMAXE + NMAX)
#define NEG_INF __int_as_float(0xff800000)

// Scratch (static device globals — allocation-free)
__device__ uint4  g_Ah4[NMAX * 32];     // fp16 feature buffer (GEMM input / gat output)
__device__ uint4  g_Bh4[NMAX * 32];     // fp16 h (gat input, layers 1-2)
__device__ float  g_B[NMAX * 32];       // fp32 h (layer 3)
__device__ uint4  g_W2h4[256 * 32];     // W2^T fp16 [N=256][K=256]
__device__ uint4  g_W3h4[32 * 32];      // W3^T fp16 [N=32][K=256]
__device__ float  g_ssrc[NMAX * 4];     // per-node src attention logits [N,H]
__device__ float  g_sdst[NMAX * 4];     // per-node dst attention logits [N,H]
__device__ int    g_csr_src[ETOTMAX];   // CSR: src ids grouped by dst
__device__ int    g_rowptr[NMAX + 1];   // CSR row pointers
__device__ int    g_wptr[NMAX];         // counts / absolute write cursors (0 at start)

__device__ __forceinline__ float pick4(float4 v, int i) {
    float ab = (i & 1) ? v.y : v.x;
    float cd = (i & 1) ? v.w : v.z;
    return (i & 2) ? cd : ab;
}

__device__ __forceinline__ void ldsm_x4(unsigned& r0, unsigned& r1, unsigned& r2,
                                        unsigned& r3, unsigned saddr) {
    asm volatile("ldmatrix.sync.aligned.m8n8.x4.shared.b16 {%0,%1,%2,%3}, [%4];"
                 : "=r"(r0), "=r"(r1), "=r"(r2), "=r"(r3) : "r"(saddr));
}

// ============== weight convert (both W2 and W3 in one launch) ==============
__global__ void w_cvt2(const float* __restrict__ W2, const float* __restrict__ W3,
                       __half* __restrict__ W2t, __half* __restrict__ W3t) {
    __shared__ float t[32][33];
    int b = blockIdx.x;
    const float* W; __half* Wt; int K, N, k0, n0;
    if (b < 64) { W = W2; Wt = W2t; K = 256; N = 256; n0 = (b & 7) * 32; k0 = (b >> 3) * 32; }
    else        { W = W3; Wt = W3t; K = 256; N = 32;  n0 = 0;            k0 = (b - 64) * 32; }
    int tx = threadIdx.x, ty = threadIdx.y;  // 32 x 8
    for (int i = ty; i < 32; i += 8) {
        int k = k0 + i, n = n0 + tx;
        t[i][tx] = (k < K && n < N) ? W[(size_t)k * N + n] : 0.f;
    }
    __syncthreads();
    for (int i = ty; i < 32; i += 8) {
        int n = n0 + i, k = k0 + tx;
        if (n < N && k < K) Wt[(size_t)n * K + k] = __float2half(t[tx][i]);
    }
}

// ============================ CSR construction ============================
// 4 edges per thread (int4 loads when aligned; E even)
__global__ void csr_count(const int* __restrict__ ei, int E) {
    int e = (blockIdx.x * blockDim.x + threadIdx.x) * 4;
    if (e + 3 < E) {
        int4 d4 = *(const int4*)&ei[E + e];
        atomicAdd(&g_wptr[d4.x], 1);
        atomicAdd(&g_wptr[d4.y], 1);
        atomicAdd(&g_wptr[d4.z], 1);
        atomicAdd(&g_wptr[d4.w], 1);
    } else {
        for (int j = 0; j < 4 && e + j < E; j++)
            atomicAdd(&g_wptr[ei[E + e + j]], 1);
    }
}

// single-block exclusive scan of (wptr[i]+1) -> rowptr; wptr := rowptr (abs cursor).
__global__ void scan_all(int n) {
    __shared__ int wsum[32];
    __shared__ int s_carry;
    int tid = threadIdx.x, lane = tid & 31, warp = tid >> 5;
    if (tid == 0) s_carry = 0;
    __syncthreads();
    int nq = (n + 3) >> 2;
    for (int base = 0; base < nq; base += 1024) {
        int i0 = (base + tid) * 4;
        int4 v4 = make_int4(0, 0, 0, 0);
        if (i0 + 3 < n) {
            v4 = *(const int4*)&g_wptr[i0];
            v4.x += 1; v4.y += 1; v4.z += 1; v4.w += 1;
        } else if (i0 < n) {
            int* vp = &v4.x;
            for (int j = 0; j < 4; j++) if (i0 + j < n) vp[j] = g_wptr[i0 + j] + 1;
        }
        int tsum = v4.x + v4.y + v4.z + v4.w;
        int x = tsum;
#pragma unroll
        for (int o = 1; o < 32; o <<= 1) {
            int t = __shfl_up_sync(0xFFFFFFFFu, x, o);
            if (lane >= o) x += t;
        }
        if (lane == 31) wsum[warp] = x;
        __syncthreads();
        if (warp == 0) {
            int s = wsum[lane];
#pragma unroll
            for (int o = 1; o < 32; o <<= 1) {
                int t = __shfl_up_sync(0xFFFFFFFFu, s, o);
                if (lane >= o) s += t;
            }
            wsum[lane] = s;
        }
        __syncthreads();
        int carry = s_carry;
        int total = wsum[31];
        int excl = carry + (warp ? wsum[warp - 1] : 0) + x - tsum;
        if (i0 + 3 < n) {
            int4 r;
            r.x = excl;
            r.y = excl + v4.x;
            r.z = r.y + v4.y;
            r.w = r.z + v4.z;
            *(int4*)&g_rowptr[i0] = r;
            *(int4*)&g_wptr[i0] = r;  // absolute write cursor = rowptr
        } else if (i0 < n) {
            int run = excl;
            int* vp = &v4.x;
            for (int j = 0; j < 4 && i0 + j < n; j++) {
                g_rowptr[i0 + j] = run; g_wptr[i0 + j] = run; run += vp[j];
            }
        }
        __syncthreads();
        if (tid == 0) s_carry = carry + total;
    }
    __syncthreads();
    if (tid == 0) g_rowptr[n] = s_carry;
}

// 4 edges per thread; absolute cursor (no rowptr load on critical path)
__global__ void csr_fill(const int* __restrict__ ei, int E, int Etot) {
    int e = (blockIdx.x * blockDim.x + threadIdx.x) * 4;
    if (e >= Etot) return;
    if (e + 3 < E) {
        int4 s4 = *(const int4*)&ei[e];
        int4 d4 = *(const int4*)&ei[E + e];
        int p0 = atomicAdd(&g_wptr[d4.x], 1);
        int p1 = atomicAdd(&g_wptr[d4.y], 1);
        int p2 = atomicAdd(&g_wptr[d4.z], 1);
        int p3 = atomicAdd(&g_wptr[d4.w], 1);
        g_csr_src[p0] = s4.x;
        g_csr_src[p1] = s4.y;
        g_csr_src[p2] = s4.z;
        g_csr_src[p3] = s4.w;
    } else {
#pragma unroll
        for (int j = 0; j < 4; j++) {
            int ee = e + j;
            if (ee >= Etot) break;
            int s, d;
            if (ee < E) { s = ei[ee]; d = ei[E + ee]; } else { s = d = ee - E; }
            int pos = atomicAdd(&g_wptr[d], 1);
            g_csr_src[pos] = s;
        }
    }
}

// ============== layer 1 GEMM + fused attention logits (fp16 h out) ==============
__global__ void gemm_l1_attn(const float* __restrict__ x, const float* __restrict__ W,
                             const float* __restrict__ asrc, const float* __restrict__ adst,
                             __half* __restrict__ out, int n) {
    __shared__ float xs[3];
    __shared__ float r1[8], r2[8];
    int node = blockIdx.x;
    if (node >= n) return;
    int tid = threadIdx.x;
    if (tid < 3) xs[tid] = x[node * 3 + tid];
    if (tid == 32) g_wptr[node] = 0;  // cursor reset for next replay
    __syncthreads();
    float acc = xs[0] * W[tid] + xs[1] * W[256 + tid] + xs[2] * W[512 + tid];
    out[(size_t)node * 256 + tid] = __float2half(acc);
    float p1 = acc * asrc[tid];
    float p2 = acc * adst[tid];
#pragma unroll
    for (int o = 16; o; o >>= 1) {
        p1 += __shfl_xor_sync(0xFFFFFFFFu, p1, o);
        p2 += __shfl_xor_sync(0xFFFFFFFFu, p2, o);
    }
    int warp = tid >> 5, lane = tid & 31;
    if (!lane) { r1[warp] = p1; r2[warp] = p2; }
    __syncthreads();
    if (tid < 4) {
        g_ssrc[node * 4 + tid] = r1[tid * 2] + r1[tid * 2 + 1];
        g_sdst[node * 4 + tid] = r2[tid * 2] + r2[tid * 2 + 1];
    }
}

// =====================================================================
// fp16 tensor-core GEMM (m16n8k16, fp32 accum), ldmatrix, K-chunk 32
// (2 sub-steps per smem stage -> half the barriers), fused attn epilogue.
// A: fp16 [M][K]; Bt: fp16 [N][K]. Layer 2: N=256.
// =====================================================================
#define APH2 40  // halves per smem row (32 data + 8 pad) = 80B; conflict-free LDSM

__global__ __launch_bounds__(256) void mma_gemm_h(
    const __half* __restrict__ A, const __half* __restrict__ Bt,
    __half* __restrict__ Ch,
    int M, int N, int K,
    const float* __restrict__ asrc, const float* __restrict__ adst,
    int C_head, int H) {
    __shared__ uint4 As4[2][128 * APH2 / 8];
    __shared__ uint4 Bs4[2][128 * APH2 / 8];

    int tid = threadIdx.x;
    int warp = tid >> 5, lane = tid & 31;
    int gid = lane >> 2, tig = lane & 3;
    int wm = warp & 3, wn = warp >> 2;
    int bm = blockIdx.x * 128, bn = blockIdx.y * 128;
    int lr = tid >> 1, lk = (tid & 1) * 16;  // row + k16 offset (2 uint4 each)

    unsigned sAs = (unsigned)__cvta_generic_to_shared(As4);
    unsigned sBs = (unsigned)__cvta_generic_to_shared(Bs4);
    const unsigned BUFB = 128u * APH2 * 2u;  // bytes per buffer (10240)
    unsigned aoff0 = ((unsigned)((wm * 32 + (lane & 15)) * APH2 + ((lane >> 4) << 3))) * 2u;
    unsigned aoff1 = aoff0 + 16u * APH2 * 2u;
    unsigned boffp[4];
#pragma unroll
    for (int p = 0; p < 4; p++) {
        int q = lane >> 3;
        int col = wn * 64 + p * 16 + ((q >> 1) << 3) + (lane & 7);
        int koff = (q & 1) << 3;
        boffp[p] = ((unsigned)(col * APH2 + koff)) * 2u;
    }

    float acc[2][8][4];
#pragma unroll
    for (int i = 0; i < 2; i++)
#pragma unroll
        for (int j = 0; j < 8; j++)
#pragma unroll
            for (int r = 0; r < 4; r++) acc[i][j][r] = 0.f;

    const uint4 z4 = make_uint4(0, 0, 0, 0);
    uint4 ra0, ra1, rb0, rb1;
    {
        bool am = bm + lr < M, bmk = bn + lr < N;
        ra0 = am ? *(const uint4*)&A[(size_t)(bm + lr) * K + lk] : z4;
        ra1 = am ? *(const uint4*)&A[(size_t)(bm + lr) * K + lk + 8] : z4;
        rb0 = bmk ? *(const uint4*)&Bt[(size_t)(bn + lr) * K + lk] : z4;
        rb1 = bmk ? *(const uint4*)&Bt[(size_t)(bn + lr) * K + lk + 8] : z4;
    }
    {
        __half* As = (__half*)As4[0];
        __half* Bs = (__half*)Bs4[0];
        *(uint4*)&As[lr * APH2 + lk] = ra0;
        *(uint4*)&As[lr * APH2 + lk + 8] = ra1;
        *(uint4*)&Bs[lr * APH2 + lk] = rb0;
        *(uint4*)&Bs[lr * APH2 + lk + 8] = rb1;
    }
    __syncthreads();

    int cur = 0;
    for (int k0 = 0; k0 < K; k0 += 32) {
        bool has_next = (k0 + 32) < K;
        if (has_next) {
            int kn = k0 + 32;
            bool am = bm + lr < M, bmk = bn + lr < N;
            ra0 = am ? *(const uint4*)&A[(size_t)(bm + lr) * K + kn + lk] : z4;
            ra1 = am ? *(const uint4*)&A[(size_t)(bm + lr) * K + kn + lk + 8] : z4;
            rb0 = bmk ? *(const uint4*)&Bt[(size_t)(bn + lr) * K + kn + lk] : z4;
            rb1 = bmk ? *(const uint4*)&Bt[(size_t)(bn + lr) * K + kn + lk + 8] : z4;
        }
        unsigned ab = sAs + (unsigned)cur * BUFB;
        unsigned bb = sBs + (unsigned)cur * BUFB;
#pragma unroll
        for (int kk = 0; kk < 2; kk++) {
            unsigned kb = kk * 32u;  // 16 halves = 32 bytes
            unsigned af[2][4], bf[8][2];
            ldsm_x4(af[0][0], af[0][1], af[0][2], af[0][3], ab + aoff0 + kb);
            ldsm_x4(af[1][0], af[1][1], af[1][2], af[1][3], ab + aoff1 + kb);
            ldsm_x4(bf[0][0], bf[0][1], bf[1][0], bf[1][1], bb + boffp[0] + kb);
            ldsm_x4(bf[2][0], bf[2][1], bf[3][0], bf[3][1], bb + boffp[1] + kb);
            ldsm_x4(bf[4][0], bf[4][1], bf[5][0], bf[5][1], bb + boffp[2] + kb);
            ldsm_x4(bf[6][0], bf[6][1], bf[7][0], bf[7][1], bb + boffp[3] + kb);
#pragma unroll
            for (int mt = 0; mt < 2; mt++)
#pragma unroll
                for (int nt = 0; nt < 8; nt++) {
                    asm volatile(
                        "mma.sync.aligned.m16n8k16.row.col.f32.f16.f16.f32 "
                        "{%0,%1,%2,%3}, {%4,%5,%6,%7}, {%8,%9}, {%0,%1,%2,%3};"
                        : "+f"(acc[mt][nt][0]), "+f"(acc[mt][nt][1]),
                          "+f"(acc[mt][nt][2]), "+f"(acc[mt][nt][3])
                        : "r"(af[mt][0]), "r"(af[mt][1]), "r"(af[mt][2]), "r"(af[mt][3]),
                          "r"(bf[nt][0]), "r"(bf[nt][1]));
                }
        }
        if (has_next) {
            int nb = cur ^ 1;
            __half* Asn = (__half*)As4[nb];
            __half* Bsn = (__half*)Bs4[nb];
            *(uint4*)&Asn[lr * APH2 + lk] = ra0;
            *(uint4*)&Asn[lr * APH2 + lk + 8] = ra1;
            *(uint4*)&Bsn[lr * APH2 + lk] = rb0;
            *(uint4*)&Bsn[lr * APH2 + lk + 8] = rb1;
            __syncthreads();
            cur = nb;
        }
    }

#pragma unroll
    for (int mt = 0; mt < 2; mt++) {
#pragma unroll
        for (int nt = 0; nt < 8; nt++) {
            int col = bn + wn * 64 + nt * 8 + 2 * tig;
            if (col >= N) continue;
            int row0 = bm + wm * 32 + mt * 16 + gid;
            if (row0 < M)
                *(__half2*)&Ch[(size_t)row0 * N + col] =
                    __float22half2_rn(make_float2(acc[mt][nt][0], acc[mt][nt][1]));
            if (row0 + 8 < M)
                *(__half2*)&Ch[(size_t)(row0 + 8) * N + col] =
                    __float22half2_rn(make_float2(acc[mt][nt][2], acc[mt][nt][3]));
        }
    }

    int wcb = bn + wn * 64;
    if (wcb < N) {
        int hd = wcb / C_head;
        float psrc[2][2] = {{0.f, 0.f}, {0.f, 0.f}};
        float pdst[2][2] = {{0.f, 0.f}, {0.f, 0.f}};
#pragma unroll
        for (int nt = 0; nt < 8; nt++) {
            int col = wcb + nt * 8 + 2 * tig;
            if (col >= N) continue;
            int cih = col - hd * C_head;
            float a0s = asrc[hd * C_head + cih], a1s = asrc[hd * C_head + cih + 1];
            float a0d = adst[hd * C_head + cih], a1d = adst[hd * C_head + cih + 1];
#pragma unroll
            for (int mt = 0; mt < 2; mt++) {
                psrc[mt][0] += acc[mt][nt][0] * a0s + acc[mt][nt][1] * a1s;
                pdst[mt][0] += acc[mt][nt][0] * a0d + acc[mt][nt][1] * a1d;
                psrc[mt][1] += acc[mt][nt][2] * a0s + acc[mt][nt][3] * a1s;
                pdst[mt][1] += acc[mt][nt][2] * a0d + acc[mt][nt][3] * a1d;
            }
        }
#pragma unroll
        for (int o = 1; o < 4; o <<= 1) {
#pragma unroll
            for (int mt = 0; mt < 2; mt++) {
#pragma unroll
                for (int hf = 0; hf < 2; hf++) {
                    psrc[mt][hf] += __shfl_xor_sync(0xFFFFFFFFu, psrc[mt][hf], o);
                    pdst[mt][hf] += __shfl_xor_sync(0xFFFFFFFFu, pdst[mt][hf], o);
                }
            }
        }
        if (tig == 0) {
#pragma unroll
            for (int mt = 0; mt < 2; mt++) {
#pragma unroll
                for (int hf = 0; hf < 2; hf++) {
                    int row = bm + wm * 32 + mt * 16 + gid + hf * 8;
                    if (row < M) {
                        g_ssrc[row * H + hd] = psrc[mt][hf];
                        g_sdst[row * H + hd] = pdst[mt][hf];
                    }
                }
            }
        }
    }
}

// =====================================================================
// Layer-3 specialized GEMM: N=32, block tile 128x32, 8 warps all on M.
// =====================================================================
#define APH 24

__global__ __launch_bounds__(256) void mma_gemm_h32(
    const __half* __restrict__ A, const __half* __restrict__ Bt,
    float* __restrict__ C, int M, int K,
    const float* __restrict__ asrc, const float* __restrict__ adst) {
    __shared__ uint4 As4[2][128 * APH / 8];
    __shared__ uint4 Bs4[2][32 * APH / 8];

    int tid = threadIdx.x;
    int warp = tid >> 5, lane = tid & 31;
    int gid = lane >> 2, tig = lane & 3;
    int wm = warp;
    int bm = blockIdx.x * 128;
    int lr = tid >> 1, lk = (tid & 1) * 8;

    unsigned sAs = (unsigned)__cvta_generic_to_shared(As4);
    unsigned sBs = (unsigned)__cvta_generic_to_shared(Bs4);
    unsigned aoff = ((unsigned)((wm * 16 + (lane & 15)) * APH + ((lane >> 4) << 3))) * 2u;
    unsigned boffp[2];
#pragma unroll
    for (int p = 0; p < 2; p++) {
        int q = lane >> 3;
        int col = p * 16 + ((q >> 1) << 3) + (lane & 7);
        int koff = (q & 1) << 3;
        boffp[p] = ((unsigned)(col * APH + koff)) * 2u;
    }

    float acc[4][4];
#pragma unroll
    for (int j = 0; j < 4; j++)
#pragma unroll
        for (int r = 0; r < 4; r++) acc[j][r] = 0.f;

    const uint4 z4 = make_uint4(0, 0, 0, 0);
    uint4 ra, rb = z4;
    ra = (bm + lr < M) ? *(const uint4*)&A[(size_t)(bm + lr) * K + lk] : z4;
    if (tid < 64) rb = *(const uint4*)&Bt[(size_t)lr * K + lk];
    {
        __half* As = (__half*)As4[0];
        *(uint4*)&As[lr * APH + lk] = ra;
        if (tid < 64) { __half* Bs = (__half*)Bs4[0]; *(uint4*)&Bs[lr * APH + lk] = rb; }
    }
    __syncthreads();

    int cur = 0;
    for (int k0 = 0; k0 < K; k0 += 16) {
        bool has_next = (k0 + 16) < K;
        if (has_next) {
            int kn = k0 + 16;
            ra = (bm + lr < M) ? *(const uint4*)&A[(size_t)(bm + lr) * K + kn + lk] : z4;
            if (tid < 64) rb = *(const uint4*)&Bt[(size_t)lr * K + kn + lk];
        }
        unsigned ab = sAs + (unsigned)cur * 6144u;
        unsigned bb = sBs + (unsigned)cur * 1536u;
        unsigned af[4], bf[4][2];
        ldsm_x4(af[0], af[1], af[2], af[3], ab + aoff);
        ldsm_x4(bf[0][0], bf[0][1], bf[1][0], bf[1][1], bb + boffp[0]);
        ldsm_x4(bf[2][0], bf[2][1], bf[3][0], bf[3][1], bb + boffp[1]);
#pragma unroll
        for (int nt = 0; nt < 4; nt++) {
            asm volatile(
                "mma.sync.aligned.m16n8k16.row.col.f32.f16.f16.f32 "
                "{%0,%1,%2,%3}, {%4,%5,%6,%7}, {%8,%9}, {%0,%1,%2,%3};"
                : "+f"(acc[nt][0]), "+f"(acc[nt][1]),
                  "+f"(acc[nt][2]), "+f"(acc[nt][3])
                : "r"(af[0]), "r"(af[1]), "r"(af[2]), "r"(af[3]),
                  "r"(bf[nt][0]), "r"(bf[nt][1]));
        }
        if (has_next) {
            int nb = cur ^ 1;
            __half* Asn = (__half*)As4[nb];
            *(uint4*)&Asn[lr * APH + lk] = ra;
            if (tid < 64) { __half* Bsn = (__half*)Bs4[nb]; *(uint4*)&Bsn[lr * APH + lk] = rb; }
            __syncthreads();
            cur = nb;
        }
    }

#pragma unroll
    for (int nt = 0; nt < 4; nt++) {
        int col = nt * 8 + 2 * tig;
        int row0 = bm + wm * 16 + gid;
        if (row0 < M)
            *(float2*)&C[(size_t)row0 * 32 + col] = make_float2(acc[nt][0], acc[nt][1]);
        if (row0 + 8 < M)
            *(float2*)&C[(size_t)(row0 + 8) * 32 + col] = make_float2(acc[nt][2], acc[nt][3]);
    }

    {
        float psrc[2] = {0.f, 0.f}, pdst[2] = {0.f, 0.f};
#pragma unroll
        for (int nt = 0; nt < 4; nt++) {
            int col = nt * 8 + 2 * tig;
            float a0s = asrc[col], a1s = asrc[col + 1];
            float a0d = adst[col], a1d = adst[col + 1];
            psrc[0] += acc[nt][0] * a0s + acc[nt][1] * a1s;
            pdst[0] += acc[nt][0] * a0d + acc[nt][1] * a1d;
            psrc[1] += acc[nt][2] * a0s + acc[nt][3] * a1s;
            pdst[1] += acc[nt][2] * a0d + acc[nt][3] * a1d;
        }
#pragma unroll
        for (int o = 1; o < 4; o <<= 1) {
#pragma unroll
            for (int hf = 0; hf < 2; hf++) {
                psrc[hf] += __shfl_xor_sync(0xFFFFFFFFu, psrc[hf], o);
                pdst[hf] += __shfl_xor_sync(0xFFFFFFFFu, pdst[hf], o);
            }
        }
        if (tig == 0) {
#pragma unroll
            for (int hf = 0; hf < 2; hf++) {
                int row = bm + wm * 16 + gid + hf * 8;
                if (row < M) { g_ssrc[row] = psrc[hf]; g_sdst[row] = pdst[hf]; }
            }
        }
    }
}

// =====================================================================
// Warp-per-node GAT propagate (H=4, C=64), fp16 in/out
// =====================================================================
template <bool FIRST>
__device__ __forceinline__ void gat4_chunk(
    const __half* __restrict__ h, int c0, int cs, float4 sd, int hd, int lane,
    float* swp, float4& m4, float4& s4, float4& acc0, float4& acc1) {
    int src = 0;
    float4 lg = make_float4(NEG_INF, NEG_INF, NEG_INF, NEG_INF);
    if (lane < cs) {
        src = g_csr_src[c0 + lane];
        float4 ss = *(const float4*)&g_ssrc[src * 4];
        lg.x = ss.x + sd.x; lg.x = lg.x >= 0.f ? lg.x : 0.2f * lg.x;
        lg.y = ss.y + sd.y; lg.y = lg.y >= 0.f ? lg.y : 0.2f * lg.y;
        lg.z = ss.z + sd.z; lg.z = lg.z >= 0.f ? lg.z : 0.2f * lg.z;
        lg.w = ss.w + sd.w; lg.w = lg.w >= 0.f ? lg.w : 0.2f * lg.w;
    }
    float4 cm = lg;
#pragma unroll
    for (int o = 16; o; o >>= 1) {
        cm.x = fmaxf(cm.x, __shfl_xor_sync(0xFFFFFFFFu, cm.x, o));
        cm.y = fmaxf(cm.y, __shfl_xor_sync(0xFFFFFFFFu, cm.y, o));
        cm.z = fmaxf(cm.z, __shfl_xor_sync(0xFFFFFFFFu, cm.z, o));
        cm.w = fmaxf(cm.w, __shfl_xor_sync(0xFFFFFFFFu, cm.w, o));
    }
    if (FIRST) {
        m4 = cm;
    } else {
        float4 mnew = make_float4(fmaxf(m4.x, cm.x), fmaxf(m4.y, cm.y),
                                  fmaxf(m4.z, cm.z), fmaxf(m4.w, cm.w));
        float4 f = make_float4(__expf(m4.x - mnew.x), __expf(m4.y - mnew.y),
                               __expf(m4.z - mnew.z), __expf(m4.w - mnew.w));
        float fh = pick4(f, hd);
        acc0.x *= fh; acc0.y *= fh; acc0.z *= fh; acc0.w *= fh;
        acc1.x *= fh; acc1.y *= fh; acc1.z *= fh; acc1.w *= fh;
        s4.x *= f.x; s4.y *= f.y; s4.z *= f.z; s4.w *= f.w;
        m4 = mnew;
    }
    float4 w = make_float4(0.f, 0.f, 0.f, 0.f);
    if (lane < cs) {
        w.x = __expf(lg.x - m4.x); w.y = __expf(lg.y - m4.y);
        w.z = __expf(lg.z - m4.z); w.w = __expf(lg.w - m4.w);
    }
    float4 ws = w;
#pragma unroll
    for (int o = 16; o; o >>= 1) {
        ws.x += __shfl_xor_sync(0xFFFFFFFFu, ws.x, o);
        ws.y += __shfl_xor_sync(0xFFFFFFFFu, ws.y, o);
        ws.z += __shfl_xor_sync(0xFFFFFFFFu, ws.z, o);
        ws.w += __shfl_xor_sync(0xFFFFFFFFu, ws.w, o);
    }
    if (FIRST) { s4 = ws; }
    else { s4.x += ws.x; s4.y += ws.y; s4.z += ws.z; s4.w += ws.w; }
    *(float4*)&swp[lane * 4] = w;
    __syncwarp();

    int e = 0;
    for (; e + 4 <= cs; e += 4) {
        int se0 = __shfl_sync(0xFFFFFFFFu, src, e);
        int se1 = __shfl_sync(0xFFFFFFFFu, src, e + 1);
        int se2 = __shfl_sync(0xFFFFFFFFu, src, e + 2);
        int se3 = __shfl_sync(0xFFFFFFFFu, src, e + 3);
        float w0 = swp[(e + 0) * 4 + hd];
        float w1 = swp[(e + 1) * 4 + hd];
        float w2 = swp[(e + 2) * 4 + hd];
        float w3 = swp[(e + 3) * 4 + hd];
        uint4 u0 = ((const uint4*)(h + (size_t)se0 * 256))[lane];
        uint4 u1 = ((const uint4*)(h + (size_t)se1 * 256))[lane];
        uint4 u2 = ((const uint4*)(h + (size_t)se2 * 256))[lane];
        uint4 u3 = ((const uint4*)(h + (size_t)se3 * 256))[lane];
#define ACC_H8(u, wgt)                                                    \
        {                                                                 \
            float2 t0 = __half22float2(*(__half2*)&(u).x);                \
            float2 t1 = __half22float2(*(__half2*)&(u).y);                \
            float2 t2 = __half22float2(*(__half2*)&(u).z);                \
            float2 t3 = __half22float2(*(__half2*)&(u).w);                \
            acc0.x += (wgt) * t0.x; acc0.y += (wgt) * t0.y;               \
            acc0.z += (wgt) * t1.x; acc0.w += (wgt) * t1.y;               \
            acc1.x += (wgt) * t2.x; acc1.y += (wgt) * t2.y;               \
            acc1.z += (wgt) * t3.x; acc1.w += (wgt) * t3.y;               \
        }
        ACC_H8(u0, w0) ACC_H8(u1, w1) ACC_H8(u2, w2) ACC_H8(u3, w3)
    }
    for (; e < cs; e++) {
        int se = __shfl_sync(0xFFFFFFFFu, src, e);
        float we = swp[e * 4 + hd];
        uint4 u = ((const uint4*)(h + (size_t)se * 256))[lane];
        ACC_H8(u, we)
    }
#undef ACC_H8
    __syncwarp();
}

__global__ __launch_bounds__(256) void gat_warp4(
    const __half* __restrict__ h, const float* __restrict__ bias,
    __half* __restrict__ out, int n, int do_relu) {
    __shared__ float sw[8][128];

    int wid = threadIdx.x >> 5, lane = threadIdx.x & 31;
    int node = blockIdx.x * 8 + wid;
    if (node >= n) return;
    int e0 = g_rowptr[node], e1 = g_rowptr[node + 1];
    float4 sd = *(const float4*)&g_sdst[node * 4];
    int hd = lane >> 3;
    float* swp = sw[wid];

    float4 m4 = make_float4(NEG_INF, NEG_INF, NEG_INF, NEG_INF);
    float4 s4 = make_float4(0.f, 0.f, 0.f, 0.f);
    float4 acc0 = make_float4(0.f, 0.f, 0.f, 0.f);
    float4 acc1 = make_float4(0.f, 0.f, 0.f, 0.f);

    gat4_chunk<true>(h, e0, min(32, e1 - e0), sd, hd, lane, swp, m4, s4, acc0, acc1);
    for (int c0 = e0 + 32; c0 < e1; c0 += 32)
        gat4_chunk<false>(h, c0, min(32, e1 - c0), sd, hd, lane, swp, m4, s4, acc0, acc1);

    float inv = 1.f / pick4(s4, hd);
    float4 b0 = *(const float4*)&bias[lane * 8];
    float4 b1 = *(const float4*)&bias[lane * 8 + 4];
    float4 o0, o1;
    o0.x = acc0.x * inv + b0.x; o0.y = acc0.y * inv + b0.y;
    o0.z = acc0.z * inv + b0.z; o0.w = acc0.w * inv + b0.w;
    o1.x = acc1.x * inv + b1.x; o1.y = acc1.y * inv + b1.y;
    o1.z = acc1.z * inv + b1.z; o1.w = acc1.w * inv + b1.w;
    if (do_relu) {
        o0.x = fmaxf(o0.x, 0.f); o0.y = fmaxf(o0.y, 0.f);
        o0.z = fmaxf(o0.z, 0.f); o0.w = fmaxf(o0.w, 0.f);
        o1.x = fmaxf(o1.x, 0.f); o1.y = fmaxf(o1.y, 0.f);
        o1.w = fmaxf(o1.w, 0.f); o1.z = fmaxf(o1.z, 0.f);
    }
    uint4 uo;
    *(__half2*)&uo.x = __float22half2_rn(make_float2(o0.x, o0.y));
    *(__half2*)&uo.y = __float22half2_rn(make_float2(o0.z, o0.w));
    *(__half2*)&uo.z = __float22half2_rn(make_float2(o1.x, o1.y));
    *(__half2*)&uo.w = __float22half2_rn(make_float2(o1.z, o1.w));
    ((uint4*)(out + (size_t)node * 256))[lane] = uo;
}

// =====================================================================
// Fused GAT propagate (H=1, C=32): warp per dst node, fp32 h (final layer)
// =====================================================================
__global__ void gat_fused1(const float* __restrict__ h, const float* __restrict__ bias,
                           float* __restrict__ out, int n) {
    int w = (blockIdx.x * blockDim.x + threadIdx.x) >> 5;
    int lane = threadIdx.x & 31;
    if (w >= n) return;
    int node = w;
    int e0 = g_rowptr[node], e1 = g_rowptr[node + 1];
    float sdst = g_sdst[node];
    float m = NEG_INF, s = 0.f, acc = 0.f;
    for (int c0 = e0; c0 < e1; c0 += 32) {
        int cs = min(32, e1 - c0);
        int src = (lane < cs) ? g_csr_src[c0 + lane] : 0;
        float v = NEG_INF;
        if (lane < cs) {
            v = g_ssrc[src] + sdst;
            v = v >= 0.f ? v : 0.2f * v;
        }
        float cm = v;
#pragma unroll
        for (int o = 16; o; o >>= 1) cm = fmaxf(cm, __shfl_xor_sync(0xFFFFFFFFu, cm, o));
        float mnew = fmaxf(m, cm);
        float f = __expf(m - mnew);
        acc *= f; s *= f; m = mnew;
        float wv = (lane < cs) ? __expf(v - m) : 0.f;
        float ps = wv;
#pragma unroll
        for (int o = 16; o; o >>= 1) ps += __shfl_xor_sync(0xFFFFFFFFu, ps, o);
        s += ps;
        int e = 0;
        for (; e + 4 <= cs; e += 4) {
            float w0 = __shfl_sync(0xFFFFFFFFu, wv, e);
            float w1 = __shfl_sync(0xFFFFFFFFu, wv, e + 1);
            float w2 = __shfl_sync(0xFFFFFFFFu, wv, e + 2);
            float w3 = __shfl_sync(0xFFFFFFFFu, wv, e + 3);
            int s0 = __shfl_sync(0xFFFFFFFFu, src, e);
            int s1 = __shfl_sync(0xFFFFFFFFu, src, e + 1);
            int s2 = __shfl_sync(0xFFFFFFFFu, src, e + 2);
            int s3 = __shfl_sync(0xFFFFFFFFu, src, e + 3);
            float v0 = h[(size_t)s0 * 32 + lane];
            float v1 = h[(size_t)s1 * 32 + lane];
            float v2 = h[(size_t)s2 * 32 + lane];
            float v3 = h[(size_t)s3 * 32 + lane];
            acc += w0 * v0 + w1 * v1 + w2 * v2 + w3 * v3;
        }
        for (; e < cs; e++) {
            float we = __shfl_sync(0xFFFFFFFFu, wv, e);
            int se = __shfl_sync(0xFFFFFFFFu, src, e);
            acc += we * h[(size_t)se * 32 + lane];
        }
    }
    out[(size_t)node * 32 + lane] = acc / s + bias[lane];
}

extern "C" void kernel_launch(void* const* d_in, const int* in_sizes, int n_in,
                              void* d_out, int out_size) {
    const float* x      = (const float*)d_in[0];
    const int*   ei     = (const int*)d_in[1];
    const float* W1     = (const float*)d_in[2];
    const float* a_src1 = (const float*)d_in[3];
    const float* a_dst1 = (const float*)d_in[4];
    const float* b1     = (const float*)d_in[5];
    const float* W2     = (const float*)d_in[6];
    const float* a_src2 = (const float*)d_in[7];
    const float* a_dst2 = (const float*)d_in[8];
    const float* b2     = (const float*)d_in[9];
    const float* W3     = (const float*)d_in[10];
    const float* a_src3 = (const float*)d_in[11];
    const float* a_dst3 = (const float*)d_in[12];
    const float* b3     = (const float*)d_in[13];
    float* out = (float*)d_out;

    int n = in_sizes[0] / 3;
    int E = in_sizes[1] / 2;
    int Etot = E + n;

    float* gB;
    __half *gAh, *gBh, *gW2h, *gW3h;
    cudaGetSymbolAddress((void**)&gB, g_B);
    cudaGetSymbolAddress((void**)&gAh, g_Ah4);
    cudaGetSymbolAddress((void**)&gBh, g_Bh4);
    cudaGetSymbolAddress((void**)&gW2h, g_W2h4);
    cudaGetSymbolAddress((void**)&gW3h, g_W3h4);

    int nw8 = (n + 7) / 8;
    dim3 g2((n + 127) / 128, 2);
    int g3 = (n + 127) / 128;

    // ---------------- weight convert + CSR build ----------------
    w_cvt2<<<72, dim3(32, 8)>>>(W2, W3, gW2h, gW3h);
    csr_count<<<(E / 4 + 255) / 256, 256>>>(ei, E);
    scan_all<<<1, 1024>>>(n);
    csr_fill<<<(Etot / 4 + 256) / 256, 256>>>(ei, E, Etot);

    // ---------------- Layer 1 ----------------
    gemm_l1_attn<<<n, 256>>>(x, W1, a_src1, a_dst1, gBh, n);
    gat_warp4<<<nw8, 256>>>(gBh, b1, gAh, n, 1);

    // ---------------- Layer 2 ----------------
    mma_gemm_h<<<g2, 256>>>(gAh, gW2h, gBh, n, 256, 256, a_src2, a_dst2, 64, 4);
    gat_warp4<<<nw8, 256>>>(gBh, b2, gAh, n, 1);

    // ---------------- Layer 3 (specialized N=32) ----------------
    mma_gemm_h32<<<g3, 256>>>(gAh, gW3h, gB, n, 256, a_src3, a_dst3);
    gat_fused1<<<(n * 32 + 255) / 256, 256>>>(gB, b3, out, n);
}